// round 8
// baseline (speedup 1.0000x reference)
#include <cuda_runtime.h>
#include <cuda_bf16.h>
#include <math.h>
#include <float.h>
#include <stdint.h>

#define S 2048
#define H 2048
#define NH 16
#define D 128
#define E 8
#define TOPK 4
#define IE 1408
#define IS 5632

// ---------------- scratch (static device globals; no allocation) --------------
__device__ float g_h[S * H];
__device__ float g_q[S * H];
__device__ float g_k[S * H];
__device__ float g_v[S * H];
__device__ float g_scores[(size_t)NH * S * S];
__device__ float g_attn[S * H];
__device__ float g_x1[S * H];
__device__ float g_h2[S * H];
__device__ float g_ch2[S * H];
__device__ float g_gb[(size_t)E * S * IE];
__device__ float g_ub[(size_t)E * S * IE];
__device__ float g_eo[(size_t)E * S * H];
__device__ float g_sgb[S * IS];
__device__ float g_sub[S * IS];
__device__ float g_sdwn[S * H];
__device__ float g_gatev[S];
__device__ int g_idx[E * S];
__device__ int g_cnt[E];
__device__ int g_tokmap[S * TOPK];
__device__ float g_tokw[S * TOPK];
// tf32-preconverted weights
__device__ float g_ceg[(size_t)E * H * IE];
__device__ float g_ceu[(size_t)E * H * IE];
__device__ float g_ced[(size_t)E * IE * H];
__device__ float g_csg[(size_t)H * IS];
__device__ float g_csu[(size_t)H * IS];
__device__ float g_csd[(size_t)IS * H];

// ================= helpers =================
__device__ __forceinline__ uint32_t smem_to_u32(const void* p) {
    uint32_t a;
    asm("{ .reg .u64 t; cvta.to.shared.u64 t, %1; cvt.u32.u64 %0, t; }"
        : "=r"(a) : "l"(p));
    return a;
}
__device__ __forceinline__ float f2tf32f(float f) {
    uint32_t r;
    asm("cvt.rna.tf32.f32 %0, %1;" : "=r"(r) : "f"(f));
    return __uint_as_float(r);
}
__device__ __forceinline__ void mma_tf32(float* d, const uint32_t* a,
                                         const uint32_t* b) {
    asm volatile(
        "mma.sync.aligned.m16n8k8.row.col.f32.tf32.tf32.f32 "
        "{%0,%1,%2,%3}, {%4,%5,%6,%7}, {%8,%9}, {%0,%1,%2,%3};"
        : "+f"(d[0]), "+f"(d[1]), "+f"(d[2]), "+f"(d[3])
        : "r"(a[0]), "r"(a[1]), "r"(a[2]), "r"(a[3]), "r"(b[0]), "r"(b[1]));
}
__device__ __forceinline__ void cp_async16(uint32_t dst, const void* src) {
    asm volatile("cp.async.ca.shared.global [%0], [%1], 16;"
                 :: "r"(dst), "l"(src));
}

// ================= tf32 mma GEMM v4 ==========================================
// CTA 128x128, 128 threads (4 warps @ 64x64), K-tile 32, 3-stage cp.async ring,
// 2 CTA/SM. Inputs must already be tf32-rounded. B is [K][N] row-major. N%128==0,
// K%32==0, nT>=3.
#define APADF 36
#define BPADF 136
#define A_STAGE_B (128 * APADF * 4)  // 18432
#define B_STAGE_B (32 * BPADF * 4)   // 17408
#define STAGE_B (A_STAGE_B + B_STAGE_B)  // 35840
#define MMA_SMEM (STAGE_B * 3)       // 107520

__global__ __launch_bounds__(128, 2)
void mma_gemm_kernel(const float* __restrict__ A, int lda, long long aStrE,
                     const float* __restrict__ B0, const float* __restrict__ B1,
                     int ldb, long long bStrE,
                     float* __restrict__ C0, float* __restrict__ C1,
                     int ldc, long long cStrE,
                     int M, int N, int K,
                     const int* __restrict__ gidxBase, int gidxStr,
                     const int* __restrict__ cntBase, int eShift) {
    extern __shared__ char smem[];
    const uint32_t sb = smem_to_u32(smem);
    const int z = blockIdx.z;
    const int e = z >> eShift;
    const int which = z & ((1 << eShift) - 1);
    const float* B = (which ? B1 : B0) + (long long)e * bStrE;
    float* C = (which ? C1 : C0) + (long long)e * cStrE;
    A += (long long)e * aStrE;

    const int cnt = cntBase ? cntBase[e] : M;
    const int mEff = min(M, cnt);
    const int row0 = blockIdx.y * 128;
    const int col0 = blockIdx.x * 128;
    if (row0 >= mEff) return;
    const int* gidx = gidxBase ? gidxBase + (long long)e * gidxStr : nullptr;

    const int tid = threadIdx.x;
    const int wid = tid >> 5;
    const int lane = tid & 31;
    const int g = lane >> 2;
    const int t4 = lane & 3;
    const int warpM = wid >> 1;  // 0..1
    const int warpN = wid & 1;   // 0..1

    // ---- load plans: per stage, 8 A-float4 + 8 B-float4 per thread ----
    // A task j: row m = (tid>>3) + 16*j, col c4 = tid&7
    const float* aG[8];
    uint32_t aS[8];
    {
        int mb = tid >> 3;
        int c4 = tid & 7;
#pragma unroll
        for (int j = 0; j < 8; j++) {
            int m = mb + 16 * j;
            int arow = row0 + m;
            int src;
            if (gidx) src = (arow < cnt) ? gidx[arow] : 0;
            else src = min(arow, M - 1);
            aG[j] = A + (size_t)src * lda + c4 * 4;
            aS[j] = sb + (uint32_t)(m * APADF + c4 * 4) * 4u;
        }
    }
    // B task j: k-row kk = (tid>>5) + 4*j, col n4 = tid&31  -> one base ptr
    const float* bG0 = B + (size_t)(tid >> 5) * ldb + col0 + (tid & 31) * 4;
    const uint32_t bS0 =
        sb + A_STAGE_B + (uint32_t)((tid >> 5) * BPADF + (tid & 31) * 4) * 4u;

    float acc[4][8][4];
#pragma unroll
    for (int mt = 0; mt < 4; mt++)
#pragma unroll
        for (int nt = 0; nt < 8; nt++)
#pragma unroll
            for (int r = 0; r < 4; r++) acc[mt][nt][r] = 0.f;

    const int nT = K / 32;
    const uint32_t stOff[3] = {0u, (uint32_t)STAGE_B, (uint32_t)(2 * STAGE_B)};

#define ISSUE(i, st)                                                   \
    do {                                                               \
        uint32_t _off = stOff[st];                                     \
        int _k0 = (i) * 32;                                            \
        _Pragma("unroll") for (int _j = 0; _j < 8; _j++) {             \
            cp_async16(aS[_j] + _off, aG[_j] + _k0);                   \
            cp_async16(bS0 + _off + (uint32_t)(_j * BPADF * 16),       \
                       bG0 + (size_t)(_k0 + 4 * _j) * ldb);            \
        }                                                              \
        asm volatile("cp.async.commit_group;");                       \
    } while (0)

    ISSUE(0, 0);
    ISSUE(1, 1);

    int stC = 0;   // stage of tile being consumed
    int stI = 2;   // stage to issue into next
    for (int i = 0; i < nT; i++) {
        if (i + 1 < nT)
            asm volatile("cp.async.wait_group 1;");
        else
            asm volatile("cp.async.wait_group 0;");
        __syncthreads();
        if (i + 2 < nT) {
            ISSUE(i + 2, stI);
            stI = (stI == 2) ? 0 : stI + 1;
        }

        const uint32_t* Asb = (const uint32_t*)(smem + stOff[stC]);
        const uint32_t* Bsb =
            (const uint32_t*)(smem + stOff[stC] + A_STAGE_B);
        stC = (stC == 2) ? 0 : stC + 1;
#pragma unroll
        for (int kk = 0; kk < 32; kk += 8) {
            uint32_t a[4][4], b[8][2];
#pragma unroll
            for (int mt = 0; mt < 4; mt++) {
                int mrow = warpM * 64 + mt * 16;
                a[mt][0] = Asb[(mrow + g) * APADF + kk + t4];
                a[mt][1] = Asb[(mrow + g + 8) * APADF + kk + t4];
                a[mt][2] = Asb[(mrow + g) * APADF + kk + t4 + 4];
                a[mt][3] = Asb[(mrow + g + 8) * APADF + kk + t4 + 4];
            }
#pragma unroll
            for (int nt = 0; nt < 8; nt++) {
                int ncol = warpN * 64 + nt * 8;
                b[nt][0] = Bsb[(kk + t4) * BPADF + ncol + g];
                b[nt][1] = Bsb[(kk + t4 + 4) * BPADF + ncol + g];
            }
#pragma unroll
            for (int mt = 0; mt < 4; mt++)
#pragma unroll
                for (int nt = 0; nt < 8; nt++)
                    mma_tf32(acc[mt][nt], a[mt], b[nt]);
        }
    }
#undef ISSUE

    // epilogue
#pragma unroll
    for (int mt = 0; mt < 4; mt++) {
        int rBase = row0 + warpM * 64 + mt * 16 + g;
#pragma unroll
        for (int half = 0; half < 2; half++) {
            int r = rBase + half * 8;
            if (r >= mEff) continue;
            float* cp = C + (size_t)r * ldc;
#pragma unroll
            for (int nt = 0; nt < 8; nt++) {
                int col = col0 + warpN * 64 + nt * 8 + t4 * 2;
                cp[col] = acc[mt][nt][half * 2 + 0];
                cp[col + 1] = acc[mt][nt][half * 2 + 1];
            }
        }
    }
}

// ---------------- bulk tf32 rounding: 6 weight tensors in one launch ---------
__global__ void cvt6_kernel(const float4* s0, float4* d0, long long n0,
                            const float4* s1, float4* d1, long long n1,
                            const float4* s2, float4* d2, long long n2,
                            const float4* s3, float4* d3, long long n3,
                            const float4* s4, float4* d4, long long n4c,
                            const float4* s5, float4* d5, long long n5) {
    const float4* src;
    float4* dst;
    long long n;
    switch (blockIdx.y) {
        case 0: src = s0; dst = d0; n = n0; break;
        case 1: src = s1; dst = d1; n = n1; break;
        case 2: src = s2; dst = d2; n = n2; break;
        case 3: src = s3; dst = d3; n = n3; break;
        case 4: src = s4; dst = d4; n = n4c; break;
        default: src = s5; dst = d5; n = n5; break;
    }
    long long i = (long long)blockIdx.x * 256 + threadIdx.x;
    if (i < n) {
        float4 v = src[i];
        v.x = f2tf32f(v.x);
        v.y = f2tf32f(v.y);
        v.z = f2tf32f(v.z);
        v.w = f2tf32f(v.w);
        dst[i] = v;
    }
}

// ---------------- RMSNorm (optional second tf32-rounded output) ----------------
__global__ void rmsnorm_kernel(const float* __restrict__ x,
                               const float* __restrict__ w,
                               float* __restrict__ out,
                               float* __restrict__ outTf) {
    const float* xr = x + (long long)blockIdx.x * H;
    float* orow = out + (long long)blockIdx.x * H;
    __shared__ float red[256];
    float s = 0.f;
    for (int j = threadIdx.x; j < H; j += 256) {
        float v = xr[j];
        s += v * v;
    }
    red[threadIdx.x] = s;
    __syncthreads();
    for (int st = 128; st > 0; st >>= 1) {
        if (threadIdx.x < st) red[threadIdx.x] += red[threadIdx.x + st];
        __syncthreads();
    }
    float inv = 1.0f / sqrtf(red[0] / (float)H + 1e-6f);
    if (outTf) {
        float* trow = outTf + (long long)blockIdx.x * H;
        for (int j = threadIdx.x; j < H; j += 256) {
            float v = w[j] * xr[j] * inv;
            orow[j] = v;
            trow[j] = f2tf32f(v);
        }
    } else {
        for (int j = threadIdx.x; j < H; j += 256) orow[j] = w[j] * xr[j] * inv;
    }
}

// ---------------- fp32 SGEMM (upstream of router) ----------------
__global__ __launch_bounds__(256, 2)
void sgemm_kernel(const float* __restrict__ A, int lda, long long sA,
                  const float* __restrict__ B, int ldb, long long sB,
                  float* __restrict__ C, int ldc, long long sC,
                  int K,
                  const float* __restrict__ bias,
                  const float* __restrict__ residual, int ldr,
                  int transB, int causal, int kLimit, float scale,
                  int selMode,
                  const float* B1, const float* B2,
                  const float* bias1, const float* bias2,
                  float* C1, float* C2) {
    __shared__ __align__(16) float As[2][8][128];
    __shared__ __align__(16) float Bs[2][8][128];

    const int bz = blockIdx.z;
    if (selMode) {
        if (bz == 1) { B = B1; bias = bias1; C = C1; }
        else if (bz == 2) { B = B2; bias = bias2; C = C2; }
    } else {
        A += (long long)bz * sA;
        B += (long long)bz * sB;
        C += (long long)bz * sC;
    }

    const int row0 = blockIdx.y * 128;
    const int col0 = blockIdx.x * 128;
    if (causal && col0 > row0) return;
    int Keff = kLimit ? min(K, row0 + 128) : K;

    const int tid = threadIdx.x;
    const int trow = (tid >> 4) * 8;
    const int tcol = (tid & 15) * 8;

    const int aRow = tid >> 1;
    const int aCol = (tid & 1) * 4;
    const int bRow = tid >> 5;
    const int bCol = (tid & 31) * 4;

    const float* Aptr = A + (long long)(row0 + aRow) * lda + aCol;
    const float* BptrNN = B + (long long)bRow * ldb + col0 + bCol;
    const float* BptrNT = B + (long long)(col0 + aRow) * ldb + aCol;

    unsigned long long acc[4][8];
#pragma unroll
    for (int i = 0; i < 4; i++)
#pragma unroll
        for (int j = 0; j < 8; j++) acc[i][j] = 0ull;

    float4 av = *reinterpret_cast<const float4*>(Aptr);
    float4 bv = transB ? *reinterpret_cast<const float4*>(BptrNT)
                       : *reinterpret_cast<const float4*>(BptrNN);
    As[0][aCol + 0][aRow] = av.x;
    As[0][aCol + 1][aRow] = av.y;
    As[0][aCol + 2][aRow] = av.z;
    As[0][aCol + 3][aRow] = av.w;
    if (transB) {
        Bs[0][aCol + 0][aRow] = bv.x;
        Bs[0][aCol + 1][aRow] = bv.y;
        Bs[0][aCol + 2][aRow] = bv.z;
        Bs[0][aCol + 3][aRow] = bv.w;
    } else {
        *reinterpret_cast<float4*>(&Bs[0][bRow][bCol]) = bv;
    }
    __syncthreads();

    int buf = 0;
    for (int k0 = 0; k0 < Keff; k0 += 8) {
        const bool more = (k0 + 8) < Keff;
        if (more) {
            av = *reinterpret_cast<const float4*>(Aptr + k0 + 8);
            bv = transB
                     ? *reinterpret_cast<const float4*>(BptrNT + k0 + 8)
                     : *reinterpret_cast<const float4*>(BptrNN + (long long)(k0 + 8) * ldb);
        }
#pragma unroll
        for (int kk = 0; kk < 8; kk++) {
            ulonglong2 a01 = *reinterpret_cast<const ulonglong2*>(&As[buf][kk][trow]);
            ulonglong2 a23 = *reinterpret_cast<const ulonglong2*>(&As[buf][kk][trow + 4]);
            float4 b0 = *reinterpret_cast<const float4*>(&Bs[buf][kk][tcol]);
            float4 b1 = *reinterpret_cast<const float4*>(&Bs[buf][kk][tcol + 4]);
            unsigned long long ap[4];
            ap[0] = a01.x; ap[1] = a01.y; ap[2] = a23.x; ap[3] = a23.y;
            float bvals[8];
            bvals[0] = b0.x; bvals[1] = b0.y; bvals[2] = b0.z; bvals[3] = b0.w;
            bvals[4] = b1.x; bvals[5] = b1.y; bvals[6] = b1.z; bvals[7] = b1.w;
#pragma unroll
            for (int j = 0; j < 8; j++) {
                unsigned long long bp;
                asm("mov.b64 %0, {%1, %1};" : "=l"(bp) : "f"(bvals[j]));
#pragma unroll
                for (int i2 = 0; i2 < 4; i2++) {
                    asm("fma.rn.f32x2 %0, %1, %2, %0;"
                        : "+l"(acc[i2][j]) : "l"(ap[i2]), "l"(bp));
                }
            }
        }
        if (more) {
            int nb = buf ^ 1;
            As[nb][aCol + 0][aRow] = av.x;
            As[nb][aCol + 1][aRow] = av.y;
            As[nb][aCol + 2][aRow] = av.z;
            As[nb][aCol + 3][aRow] = av.w;
            if (transB) {
                Bs[nb][aCol + 0][aRow] = bv.x;
                Bs[nb][aCol + 1][aRow] = bv.y;
                Bs[nb][aCol + 2][aRow] = bv.z;
                Bs[nb][aCol + 3][aRow] = bv.w;
            } else {
                *reinterpret_cast<float4*>(&Bs[nb][bRow][bCol]) = bv;
            }
        }
        __syncthreads();
        buf ^= 1;
    }

#pragma unroll
    for (int i2 = 0; i2 < 4; i2++) {
#pragma unroll
        for (int j = 0; j < 8; j++) {
            float lo, hi;
            asm("mov.b64 {%0, %1}, %2;" : "=f"(lo), "=f"(hi) : "l"(acc[i2][j]));
            int c = col0 + tcol + j;
#pragma unroll
            for (int half = 0; half < 2; half++) {
                int r = row0 + trow + 2 * i2 + half;
                float v = (half == 0 ? lo : hi) * scale;
                if (bias) v += bias[c];
                if (residual) v += residual[(long long)r * ldr + c];
                C[(long long)r * ldc + c] = v;
            }
        }
    }
}

// ---------------- RoPE (fp32, fast) ----------------
__global__ void rope_kernel(float* __restrict__ q, float* __restrict__ k) {
    int s = blockIdx.x;
    int h = blockIdx.y;
    int j = threadIdx.x;  // 0..63
    // inv = 1e6^(-j/64) = exp2(-j * log2(1e6)/64)
    float inv = exp2f(-(float)j * 0.31143075889569023f);
    float ang = (float)s * inv;
    float c, sn;
    sincosf(ang, &sn, &c);
    long long base = ((long long)s * NH + h) * D;
    float q1 = q[base + j], q2 = q[base + j + 64];
    q[base + j] = q1 * c - q2 * sn;
    q[base + j + 64] = q2 * c + q1 * sn;
    float k1 = k[base + j], k2 = k[base + j + 64];
    k[base + j] = k1 * c - k2 * sn;
    k[base + j + 64] = k2 * c + k1 * sn;
}

// ---------------- causal row softmax ----------------
__global__ void softmax_kernel(float* __restrict__ scores) {
    int r = blockIdx.x;
    float* row = scores + ((long long)blockIdx.y * S + r) * S;
    const int limit = r + 1;
    const int rBlk = ((r >> 7) + 1) << 7;
    __shared__ float red[256];
    int tid = threadIdx.x;
    float m = -FLT_MAX;
    for (int j = tid; j < limit; j += 256) m = fmaxf(m, row[j]);
    red[tid] = m;
    __syncthreads();
    for (int st = 128; st > 0; st >>= 1) {
        if (tid < st) red[tid] = fmaxf(red[tid], red[tid + st]);
        __syncthreads();
    }
    m = red[0];
    __syncthreads();
    float sum = 0.f;
    for (int j = tid; j < limit; j += 256) {
        float e = expf(row[j] - m);
        row[j] = e;
        sum += e;
    }
    red[tid] = sum;
    __syncthreads();
    for (int st = 128; st > 0; st >>= 1) {
        if (tid < st) red[tid] += red[tid + st];
        __syncthreads();
    }
    float inv = 1.0f / red[0];
    for (int j = tid; j < limit; j += 256) row[j] *= inv;
    for (int j = limit + tid; j < rBlk; j += 256) row[j] = 0.f;
}

// ---------------- router ----------------
__global__ void router_kernel(const float* __restrict__ h2,
                              const float* __restrict__ gate_w,
                              float* __restrict__ logits_out,
                              int* __restrict__ idxbuf,
                              int* __restrict__ cnt,
                              int* __restrict__ tokmap,
                              float* __restrict__ tokw) {
    int s = blockIdx.x;
    const float* hr = h2 + (long long)s * H;
    __shared__ float red[256][E];
    float p[E];
#pragma unroll
    for (int e = 0; e < E; e++) p[e] = 0.f;
    for (int j = threadIdx.x; j < H; j += 256) {
        float hv = hr[j];
#pragma unroll
        for (int e = 0; e < E; e++) p[e] += hv * gate_w[j * E + e];
    }
#pragma unroll
    for (int e = 0; e < E; e++) red[threadIdx.x][e] = p[e];
    __syncthreads();
    for (int st = 128; st > 0; st >>= 1) {
        if (threadIdx.x < st)
#pragma unroll
            for (int e = 0; e < E; e++) red[threadIdx.x][e] += red[threadIdx.x + st][e];
        __syncthreads();
    }
    if (threadIdx.x == 0) {
        float logit[E];
        float m = -FLT_MAX;
#pragma unroll
        for (int e = 0; e < E; e++) {
            logit[e] = red[0][e];
            logits_out[(long long)s * E + e] = logit[e];
            m = fmaxf(m, logit[e]);
        }
        float sum = 0.f, rw[E];
#pragma unroll
        for (int e = 0; e < E; e++) {
            rw[e] = expf(logit[e] - m);
            sum += rw[e];
        }
        float inv = 1.0f / sum;
#pragma unroll
        for (int e = 0; e < E; e++) rw[e] *= inv;
        bool used[E];
#pragma unroll
        for (int e = 0; e < E; e++) used[e] = false;
        for (int k = 0; k < TOPK; k++) {
            int best = -1;
            float bvv = -FLT_MAX;
            for (int e = 0; e < E; e++)
                if (!used[e] && rw[e] > bvv) { bvv = rw[e]; best = e; }
            used[best] = true;
            int pos = atomicAdd(&cnt[best], 1);
            idxbuf[best * S + pos] = s;
            tokmap[s * TOPK + k] = best * S + pos;
            tokw[s * TOPK + k] = bvv;
        }
    }
}

// ---------------- h2 . sgate ----------------
__global__ void rowdot_kernel(const float* __restrict__ h2,
                              const float* __restrict__ sgate,
                              float* __restrict__ gatev) {
    int s = blockIdx.x;
    const float* hr = h2 + (long long)s * H;
    __shared__ float red[256];
    float acc = 0.f;
    for (int j = threadIdx.x; j < H; j += 256) acc += hr[j] * sgate[j];
    red[threadIdx.x] = acc;
    __syncthreads();
    for (int st = 128; st > 0; st >>= 1) {
        if (threadIdx.x < st) red[threadIdx.x] += red[threadIdx.x + st];
        __syncthreads();
    }
    if (threadIdx.x == 0) gatev[s] = red[0];
}

// ---------------- silu(g)*u, experts (output tf32-rounded) ----------------
__global__ void silu_mul_expert_kernel(float* __restrict__ gb,
                                       const float* __restrict__ ub,
                                       const int* __restrict__ cnt) {
    int e = blockIdx.y;
    long long i = (long long)blockIdx.x * 256 + threadIdx.x;
    long long lim = (long long)cnt[e] * IE;
    if (i >= lim) return;
    size_t o = (size_t)e * S * IE + i;
    float x = gb[o];
    float sg = 1.0f / (1.0f + expf(-x));
    gb[o] = f2tf32f(x * sg * ub[o]);
}

// ---------------- silu(g)*u shared (output tf32-rounded) ----------------
__global__ void silu_mul_kernel(float* __restrict__ g, const float* __restrict__ u,
                                long long n) {
    long long i = (long long)blockIdx.x * 256 + threadIdx.x;
    if (i < n) {
        float x = g[i];
        float sg = 1.0f / (1.0f + expf(-x));
        g[i] = f2tf32f(x * sg * u[i]);
    }
}

// ---------------- final combine ----------------
__global__ void final_kernel(const float* __restrict__ x1,
                             const float* __restrict__ eo,
                             const int* __restrict__ tokmap,
                             const float* __restrict__ tokw,
                             const float* __restrict__ sdwn,
                             const float* __restrict__ gatev,
                             float* __restrict__ out) {
    long long i = (long long)blockIdx.x * 256 + threadIdx.x;
    int s = (int)(i / H);
    int c = (int)(i % H);
    float gv = 1.0f / (1.0f + expf(-gatev[s]));
    float acc = x1[i] + gv * sdwn[i];
#pragma unroll
    for (int j = 0; j < TOPK; j++) {
        int row = tokmap[s * TOPK + j];
        acc += tokw[s * TOPK + j] * eo[(size_t)row * H + c];
    }
    out[i] = acc;
}

// ---------------- host ----------------
static void launch_mma(const float* A, int lda, long long aStrE,
                       const float* B0, const float* B1, int ldb, long long bStrE,
                       float* C0, float* C1, int ldc, long long cStrE,
                       int M, int N, int K,
                       const int* gidx, int gstr, const int* cnt, int eShift,
                       int nz) {
    dim3 grid(N / 128, (M + 127) / 128, nz);
    mma_gemm_kernel<<<grid, 128, MMA_SMEM>>>(A, lda, aStrE, B0, B1, ldb, bStrE,
                                             C0, C1, ldc, cStrE, M, N, K,
                                             gidx, gstr, cnt, eShift);
}

extern "C" void kernel_launch(void* const* d_in, const int* in_sizes, int n_in,
                              void* d_out, int out_size) {
    (void)in_sizes; (void)n_in; (void)out_size;
    const float* x     = (const float*)d_in[0];
    const float* ln1   = (const float*)d_in[1];
    const float* ln2   = (const float*)d_in[2];
    const float* wq    = (const float*)d_in[3];
    const float* bq    = (const float*)d_in[4];
    const float* wk    = (const float*)d_in[5];
    const float* bk    = (const float*)d_in[6];
    const float* wv    = (const float*)d_in[7];
    const float* bv    = (const float*)d_in[8];
    const float* wo    = (const float*)d_in[9];
    const float* gatew = (const float*)d_in[10];
    const float* eg    = (const float*)d_in[11];
    const float* eu    = (const float*)d_in[12];
    const float* ed    = (const float*)d_in[13];
    const float* sg    = (const float*)d_in[14];
    const float* su    = (const float*)d_in[15];
    const float* sd    = (const float*)d_in[16];
    const float* sgate = (const float*)d_in[17];
    float* out = (float*)d_out;

    cudaFuncSetAttribute(mma_gemm_kernel,
                         cudaFuncAttributeMaxDynamicSharedMemorySize, MMA_SMEM);

    float *h, *q, *k, *v, *scores, *attn, *x1, *h2, *ch2, *gb, *ub, *eo, *sgb,
        *sub, *sdwn, *gatev, *tokw;
    float *ceg, *ceu, *ced, *csg, *csu, *csd;
    int *idx, *cnt, *tokmap;
    cudaGetSymbolAddress((void**)&h, g_h);
    cudaGetSymbolAddress((void**)&q, g_q);
    cudaGetSymbolAddress((void**)&k, g_k);
    cudaGetSymbolAddress((void**)&v, g_v);
    cudaGetSymbolAddress((void**)&scores, g_scores);
    cudaGetSymbolAddress((void**)&attn, g_attn);
    cudaGetSymbolAddress((void**)&x1, g_x1);
    cudaGetSymbolAddress((void**)&h2, g_h2);
    cudaGetSymbolAddress((void**)&ch2, g_ch2);
    cudaGetSymbolAddress((void**)&gb, g_gb);
    cudaGetSymbolAddress((void**)&ub, g_ub);
    cudaGetSymbolAddress((void**)&eo, g_eo);
    cudaGetSymbolAddress((void**)&sgb, g_sgb);
    cudaGetSymbolAddress((void**)&sub, g_sub);
    cudaGetSymbolAddress((void**)&sdwn, g_sdwn);
    cudaGetSymbolAddress((void**)&gatev, g_gatev);
    cudaGetSymbolAddress((void**)&idx, g_idx);
    cudaGetSymbolAddress((void**)&cnt, g_cnt);
    cudaGetSymbolAddress((void**)&tokmap, g_tokmap);
    cudaGetSymbolAddress((void**)&tokw, g_tokw);
    cudaGetSymbolAddress((void**)&ceg, g_ceg);
    cudaGetSymbolAddress((void**)&ceu, g_ceu);
    cudaGetSymbolAddress((void**)&ced, g_ced);
    cudaGetSymbolAddress((void**)&csg, g_csg);
    cudaGetSymbolAddress((void**)&csu, g_csu);
    cudaGetSymbolAddress((void**)&csd, g_csd);

    const float ascale = 0.08838834764831845f;

    // 0. pre-round all MoE/shared weights to tf32 in ONE launch
    {
        long long nEG = (long long)E * H * IE / 4;
        long long nED = (long long)E * IE * H / 4;
        long long nSG = (long long)H * IS / 4;
        long long nSD = (long long)IS * H / 4;
        unsigned gx = (unsigned)((nEG + 255) / 256);
        dim3 grid(gx, 6);
        cvt6_kernel<<<grid, 256>>>((const float4*)eg, (float4*)ceg, nEG,
                                   (const float4*)eu, (float4*)ceu, nEG,
                                   (const float4*)ed, (float4*)ced, nED,
                                   (const float4*)sg, (float4*)csg, nSG,
                                   (const float4*)su, (float4*)csu, nSG,
                                   (const float4*)sd, (float4*)csd, nSD);
    }

    // 1. h = rmsnorm(x, ln1)
    rmsnorm_kernel<<<S, 256>>>(x, ln1, h, nullptr);

    // 2. q,k,v (batched fp32)
    {
        dim3 grid((NH * D) / 128, S / 128, 3);
        sgemm_kernel<<<grid, 256>>>(h, H, 0, wq, NH * D, 0, q, NH * D, 0, H,
                                    bq, nullptr, 0, 0, 0, 0, 1.0f,
                                    1, wk, wv, bk, bv, k, v);
    }

    // 3. RoPE
    rope_kernel<<<dim3(S, NH), 64>>>(q, k);

    // 4. scores
    {
        dim3 grid(S / 128, S / 128, NH);
        sgemm_kernel<<<grid, 256>>>(q, NH * D, D, k, NH * D, D, scores, S,
                                    (long long)S * S, D, nullptr, nullptr, 0,
                                    1, 1, 0, ascale,
                                    0, nullptr, nullptr, nullptr, nullptr,
                                    nullptr, nullptr);
    }

    // 5. softmax
    softmax_kernel<<<dim3(S, NH), 256>>>(scores);

    // 6. attn = probs @ v
    {
        dim3 grid(D / 128, S / 128, NH);
        sgemm_kernel<<<grid, 256>>>(scores, S, (long long)S * S, v, NH * D, D,
                                    attn, NH * D, D, S, nullptr, nullptr, 0,
                                    0, 0, 1, 1.0f,
                                    0, nullptr, nullptr, nullptr, nullptr,
                                    nullptr, nullptr);
    }

    // 7. x1 = x + attn @ wo
    {
        dim3 grid(H / 128, S / 128, 1);
        sgemm_kernel<<<grid, 256>>>(attn, NH * D, 0, wo, H, 0, x1, H, 0,
                                    NH * D, nullptr, x, H, 0, 0, 0, 1.0f,
                                    0, nullptr, nullptr, nullptr, nullptr,
                                    nullptr, nullptr);
    }

    // 8. h2 = rmsnorm(x1, ln2) + tf32 copy (fused)
    rmsnorm_kernel<<<S, 256>>>(x1, ln2, h2, ch2);

    // 9. router (exact h2)
    cudaMemsetAsync(cnt, 0, E * sizeof(int));
    router_kernel<<<S, 256>>>(h2, gatew, out + (long long)S * H, idx, cnt,
                              tokmap, tokw);

    // 10. MoE gate+up (z = 2E)
    launch_mma(ch2, H, 0, ceg, ceu, IE, (long long)H * IE,
               gb, ub, IE, (long long)S * IE, S, IE, H, idx, S, cnt, 1, 2 * E);

    // 11. silu (+tf32 round)
    {
        dim3 grid((unsigned)(((long long)S * IE + 255) / 256), E);
        silu_mul_expert_kernel<<<grid, 256>>>(gb, ub, cnt);
    }

    // 12. MoE down (z = E)
    launch_mma(gb, IE, (long long)S * IE, ced, nullptr, H, (long long)IE * H,
               eo, nullptr, H, (long long)S * H, S, H, IE, nullptr, 0, cnt, 0, E);

    // 13. shared expert
    launch_mma(ch2, H, 0, csg, csu, IS, 0, sgb, sub, IS, 0, S, IS, H,
               nullptr, 0, nullptr, 1, 2);
    {
        long long n = (long long)S * IS;
        silu_mul_kernel<<<(unsigned)((n + 255) / 256), 256>>>(sgb, sub, n);
    }
    launch_mma(sgb, IS, 0, csd, nullptr, H, 0, sdwn, nullptr, H, 0, S, H, IS,
               nullptr, 0, nullptr, 0, 1);

    // 14. gate scalar
    rowdot_kernel<<<S, 256>>>(h2, sgate, gatev);

    // 15. combine
    final_kernel<<<(S * H) / 256, 256>>>(x1, eo, tokmap, tokw, sdwn, gatev, out);
}

// round 9
// speedup vs baseline: 1.0881x; 1.0881x over previous
#include <cuda_runtime.h>
#include <cuda_bf16.h>
#include <math.h>
#include <float.h>
#include <stdint.h>

#define S 2048
#define H 2048
#define NH 16
#define D 128
#define E 8
#define TOPK 4
#define IE 1408
#define IS 5632

// ---------------- scratch (static device globals; no allocation) --------------
__device__ float g_h[S * H];
__device__ float g_q[S * H];
__device__ float g_k[S * H];
__device__ float g_v[S * H];
__device__ float g_scores[(size_t)NH * S * S];
__device__ float g_attn[S * H];
__device__ float g_x1[S * H];
__device__ float g_h2[S * H];
__device__ float g_ch2[S * H];
__device__ float g_gb[(size_t)E * S * IE];
__device__ float g_ub[(size_t)E * S * IE];
__device__ float g_eo[(size_t)E * S * H];
__device__ float g_sgb[S * IS];
__device__ float g_sub[S * IS];
__device__ float g_sdwn[S * H];
__device__ float g_gatev[S];
__device__ int g_idx[E * S];
__device__ int g_cnt[E];
__device__ int g_tokmap[S * TOPK];
__device__ float g_tokw[S * TOPK];
// tf32-preconverted weights
__device__ float g_ceg[(size_t)E * H * IE];
__device__ float g_ceu[(size_t)E * H * IE];
__device__ float g_ced[(size_t)E * IE * H];
__device__ float g_csg[(size_t)H * IS];
__device__ float g_csu[(size_t)H * IS];
__device__ float g_csd[(size_t)IS * H];

// ================= helpers =================
__device__ __forceinline__ uint32_t smem_to_u32(const void* p) {
    uint32_t a;
    asm("{ .reg .u64 t; cvta.to.shared.u64 t, %1; cvt.u32.u64 %0, t; }"
        : "=r"(a) : "l"(p));
    return a;
}
__device__ __forceinline__ float f2tf32f(float f) {
    uint32_t r;
    asm("cvt.rna.tf32.f32 %0, %1;" : "=r"(r) : "f"(f));
    return __uint_as_float(r);
}
__device__ __forceinline__ void mma_tf32(float* d, const uint32_t* a,
                                         const uint32_t* b) {
    asm volatile(
        "mma.sync.aligned.m16n8k8.row.col.f32.tf32.tf32.f32 "
        "{%0,%1,%2,%3}, {%4,%5,%6,%7}, {%8,%9}, {%0,%1,%2,%3};"
        : "+f"(d[0]), "+f"(d[1]), "+f"(d[2]), "+f"(d[3])
        : "r"(a[0]), "r"(a[1]), "r"(a[2]), "r"(a[3]), "r"(b[0]), "r"(b[1]));
}
__device__ __forceinline__ void cp_async16(uint32_t dst, const void* src) {
    asm volatile("cp.async.ca.shared.global [%0], [%1], 16;"
                 :: "r"(dst), "l"(src));
}

// ================= tf32 mma GEMM v3 ==========================================
// CTA 128x128, 128 threads (4 warps @ 64x64), 4-stage cp.async ring, 2 CTA/SM.
// Inputs must already be tf32-rounded fp32. B is [K][N] row-major. N%128==0.
#define APADF 20
#define BPADF 136
#define A_STAGE_B (128 * APADF * 4)  // 10240
#define B_STAGE_B (16 * BPADF * 4)   // 8704
#define STAGE_B (A_STAGE_B + B_STAGE_B)
#define NSTAGE 4
#define MMA_SMEM (STAGE_B * NSTAGE)  // 75776

__global__ __launch_bounds__(128, 2)
void mma_gemm_kernel(const float* __restrict__ A, int lda, long long aStrE,
                     const float* __restrict__ B0, const float* __restrict__ B1,
                     int ldb, long long bStrE,
                     float* __restrict__ C0, float* __restrict__ C1,
                     int ldc, long long cStrE,
                     int M, int N, int K,
                     const int* __restrict__ gidxBase, int gidxStr,
                     const int* __restrict__ cntBase, int eShift) {
    extern __shared__ char smem[];
    const uint32_t sb = smem_to_u32(smem);
    const int z = blockIdx.z;
    const int e = z >> eShift;
    const int which = z & ((1 << eShift) - 1);
    const float* B = (which ? B1 : B0) + (long long)e * bStrE;
    float* C = (which ? C1 : C0) + (long long)e * cStrE;
    A += (long long)e * aStrE;

    const int cnt = cntBase ? cntBase[e] : M;
    const int mEff = min(M, cnt);
    const int row0 = blockIdx.y * 128;
    const int col0 = blockIdx.x * 128;
    if (row0 >= mEff) return;
    const int* gidx = gidxBase ? gidxBase + (long long)e * gidxStr : nullptr;

    const int tid = threadIdx.x;
    const int wid = tid >> 5;
    const int lane = tid & 31;
    const int g = lane >> 2;
    const int t4 = lane & 3;
    const int warpM = wid >> 1;  // 0..1
    const int warpN = wid & 1;   // 0..1

    // ---- cp.async task plans (4 A-f4 + 4 B-f4 per thread per stage) ----
    const float* aG[4];
    uint32_t aS[4];
#pragma unroll
    for (int j = 0; j < 4; j++) {
        int u = tid + 128 * j;
        int m = u >> 2, c4 = u & 3;
        int arow = row0 + m;
        int src;
        if (gidx) src = (arow < cnt) ? gidx[arow] : 0;
        else src = min(arow, M - 1);
        aG[j] = A + (size_t)src * lda + c4 * 4;
        aS[j] = sb + (uint32_t)(m * APADF + c4 * 4) * 4u;
    }
    const float* bG[4];
    uint32_t bS[4];
#pragma unroll
    for (int j = 0; j < 4; j++) {
        int u = tid + 128 * j;
        int n4 = u & 31, kk = u >> 5;
        bG[j] = B + (size_t)kk * ldb + col0 + n4 * 4;
        bS[j] = sb + A_STAGE_B + (uint32_t)(kk * BPADF + n4 * 4) * 4u;
    }

    float acc[4][8][4];
#pragma unroll
    for (int mt = 0; mt < 4; mt++)
#pragma unroll
        for (int nt = 0; nt < 8; nt++)
#pragma unroll
            for (int r = 0; r < 4; r++) acc[mt][nt][r] = 0.f;

    const int nT = K / 16;

#define ISSUE(i)                                                      \
    do {                                                              \
        uint32_t _off = (uint32_t)((i) & 3) * STAGE_B;                \
        int _k0 = (i) * 16;                                           \
        cp_async16(aS[0] + _off, aG[0] + _k0);                        \
        cp_async16(aS[1] + _off, aG[1] + _k0);                        \
        cp_async16(aS[2] + _off, aG[2] + _k0);                        \
        cp_async16(aS[3] + _off, aG[3] + _k0);                        \
        cp_async16(bS[0] + _off, bG[0] + (size_t)_k0 * ldb);          \
        cp_async16(bS[1] + _off, bG[1] + (size_t)_k0 * ldb);          \
        cp_async16(bS[2] + _off, bG[2] + (size_t)_k0 * ldb);          \
        cp_async16(bS[3] + _off, bG[3] + (size_t)_k0 * ldb);          \
        asm volatile("cp.async.commit_group;");                       \
    } while (0)

    ISSUE(0);
    if (nT > 1) ISSUE(1);
    if (nT > 2) ISSUE(2);

    for (int i = 0; i < nT; i++) {
        const int rem = nT - 1 - i;  // groups issued after stage i
        if (rem >= 2)
            asm volatile("cp.async.wait_group 2;");
        else if (rem == 1)
            asm volatile("cp.async.wait_group 1;");
        else
            asm volatile("cp.async.wait_group 0;");
        __syncthreads();
        if (i + 3 < nT) ISSUE(i + 3);

        const uint32_t* Asb =
            (const uint32_t*)(smem + (size_t)(i & 3) * STAGE_B);
        const uint32_t* Bsb =
            (const uint32_t*)(smem + (size_t)(i & 3) * STAGE_B + A_STAGE_B);
#pragma unroll
        for (int kk = 0; kk < 16; kk += 8) {
            uint32_t a[4][4], b[8][2];
#pragma unroll
            for (int mt = 0; mt < 4; mt++) {
                int mrow = warpM * 64 + mt * 16;
                a[mt][0] = Asb[(mrow + g) * APADF + kk + t4];
                a[mt][1] = Asb[(mrow + g + 8) * APADF + kk + t4];
                a[mt][2] = Asb[(mrow + g) * APADF + kk + t4 + 4];
                a[mt][3] = Asb[(mrow + g + 8) * APADF + kk + t4 + 4];
            }
#pragma unroll
            for (int nt = 0; nt < 8; nt++) {
                int ncol = warpN * 64 + nt * 8;
                b[nt][0] = Bsb[(kk + t4) * BPADF + ncol + g];
                b[nt][1] = Bsb[(kk + t4 + 4) * BPADF + ncol + g];
            }
#pragma unroll
            for (int mt = 0; mt < 4; mt++)
#pragma unroll
                for (int nt = 0; nt < 8; nt++)
                    mma_tf32(acc[mt][nt], a[mt], b[nt]);
        }
    }
#undef ISSUE

    // epilogue
#pragma unroll
    for (int mt = 0; mt < 4; mt++) {
        int rBase = row0 + warpM * 64 + mt * 16 + g;
#pragma unroll
        for (int half = 0; half < 2; half++) {
            int r = rBase + half * 8;
            if (r >= mEff) continue;
            float* cp = C + (size_t)r * ldc;
#pragma unroll
            for (int nt = 0; nt < 8; nt++) {
                int col = col0 + warpN * 64 + nt * 8 + t4 * 2;
                cp[col] = acc[mt][nt][half * 2 + 0];
                cp[col + 1] = acc[mt][nt][half * 2 + 1];
            }
        }
    }
}

// ---------------- bulk tf32 rounding: 6 weight tensors in one launch ---------
__global__ void cvt6_kernel(const float4* s0, float4* d0, long long n0,
                            const float4* s1, float4* d1, long long n1,
                            const float4* s2, float4* d2, long long n2,
                            const float4* s3, float4* d3, long long n3,
                            const float4* s4, float4* d4, long long n4c,
                            const float4* s5, float4* d5, long long n5) {
    const float4* src;
    float4* dst;
    long long n;
    switch (blockIdx.y) {
        case 0: src = s0; dst = d0; n = n0; break;
        case 1: src = s1; dst = d1; n = n1; break;
        case 2: src = s2; dst = d2; n = n2; break;
        case 3: src = s3; dst = d3; n = n3; break;
        case 4: src = s4; dst = d4; n = n4c; break;
        default: src = s5; dst = d5; n = n5; break;
    }
    long long i = (long long)blockIdx.x * 256 + threadIdx.x;
    if (i < n) {
        float4 v = src[i];
        v.x = f2tf32f(v.x);
        v.y = f2tf32f(v.y);
        v.z = f2tf32f(v.z);
        v.w = f2tf32f(v.w);
        dst[i] = v;
    }
}

// ---------------- RMSNorm (optional second tf32-rounded output) ----------------
__global__ void rmsnorm_kernel(const float* __restrict__ x,
                               const float* __restrict__ w,
                               float* __restrict__ out,
                               float* __restrict__ outTf) {
    const float* xr = x + (long long)blockIdx.x * H;
    float* orow = out + (long long)blockIdx.x * H;
    __shared__ float red[256];
    float s = 0.f;
    for (int j = threadIdx.x; j < H; j += 256) {
        float v = xr[j];
        s += v * v;
    }
    red[threadIdx.x] = s;
    __syncthreads();
    for (int st = 128; st > 0; st >>= 1) {
        if (threadIdx.x < st) red[threadIdx.x] += red[threadIdx.x + st];
        __syncthreads();
    }
    float inv = 1.0f / sqrtf(red[0] / (float)H + 1e-6f);
    if (outTf) {
        float* trow = outTf + (long long)blockIdx.x * H;
        for (int j = threadIdx.x; j < H; j += 256) {
            float v = w[j] * xr[j] * inv;
            orow[j] = v;
            trow[j] = f2tf32f(v);
        }
    } else {
        for (int j = threadIdx.x; j < H; j += 256) orow[j] = w[j] * xr[j] * inv;
    }
}

// ---------------- fp32 SGEMM (upstream of router) ----------------
__global__ __launch_bounds__(256, 2)
void sgemm_kernel(const float* __restrict__ A, int lda, long long sA,
                  const float* __restrict__ B, int ldb, long long sB,
                  float* __restrict__ C, int ldc, long long sC,
                  int K,
                  const float* __restrict__ bias,
                  const float* __restrict__ residual, int ldr,
                  int transB, int causal, int kLimit, float scale,
                  int selMode,
                  const float* B1, const float* B2,
                  const float* bias1, const float* bias2,
                  float* C1, float* C2) {
    __shared__ __align__(16) float As[2][8][128];
    __shared__ __align__(16) float Bs[2][8][128];

    const int bz = blockIdx.z;
    if (selMode) {
        if (bz == 1) { B = B1; bias = bias1; C = C1; }
        else if (bz == 2) { B = B2; bias = bias2; C = C2; }
    } else {
        A += (long long)bz * sA;
        B += (long long)bz * sB;
        C += (long long)bz * sC;
    }

    const int row0 = blockIdx.y * 128;
    const int col0 = blockIdx.x * 128;
    if (causal && col0 > row0) return;
    int Keff = kLimit ? min(K, row0 + 128) : K;

    const int tid = threadIdx.x;
    const int trow = (tid >> 4) * 8;
    const int tcol = (tid & 15) * 8;

    const int aRow = tid >> 1;
    const int aCol = (tid & 1) * 4;
    const int bRow = tid >> 5;
    const int bCol = (tid & 31) * 4;

    const float* Aptr = A + (long long)(row0 + aRow) * lda + aCol;
    const float* BptrNN = B + (long long)bRow * ldb + col0 + bCol;
    const float* BptrNT = B + (long long)(col0 + aRow) * ldb + aCol;

    unsigned long long acc[4][8];
#pragma unroll
    for (int i = 0; i < 4; i++)
#pragma unroll
        for (int j = 0; j < 8; j++) acc[i][j] = 0ull;

    float4 av = *reinterpret_cast<const float4*>(Aptr);
    float4 bv = transB ? *reinterpret_cast<const float4*>(BptrNT)
                       : *reinterpret_cast<const float4*>(BptrNN);
    As[0][aCol + 0][aRow] = av.x;
    As[0][aCol + 1][aRow] = av.y;
    As[0][aCol + 2][aRow] = av.z;
    As[0][aCol + 3][aRow] = av.w;
    if (transB) {
        Bs[0][aCol + 0][aRow] = bv.x;
        Bs[0][aCol + 1][aRow] = bv.y;
        Bs[0][aCol + 2][aRow] = bv.z;
        Bs[0][aCol + 3][aRow] = bv.w;
    } else {
        *reinterpret_cast<float4*>(&Bs[0][bRow][bCol]) = bv;
    }
    __syncthreads();

    int buf = 0;
    for (int k0 = 0; k0 < Keff; k0 += 8) {
        const bool more = (k0 + 8) < Keff;
        if (more) {
            av = *reinterpret_cast<const float4*>(Aptr + k0 + 8);
            bv = transB
                     ? *reinterpret_cast<const float4*>(BptrNT + k0 + 8)
                     : *reinterpret_cast<const float4*>(BptrNN + (long long)(k0 + 8) * ldb);
        }
#pragma unroll
        for (int kk = 0; kk < 8; kk++) {
            ulonglong2 a01 = *reinterpret_cast<const ulonglong2*>(&As[buf][kk][trow]);
            ulonglong2 a23 = *reinterpret_cast<const ulonglong2*>(&As[buf][kk][trow + 4]);
            float4 b0 = *reinterpret_cast<const float4*>(&Bs[buf][kk][tcol]);
            float4 b1 = *reinterpret_cast<const float4*>(&Bs[buf][kk][tcol + 4]);
            unsigned long long ap[4];
            ap[0] = a01.x; ap[1] = a01.y; ap[2] = a23.x; ap[3] = a23.y;
            float bvals[8];
            bvals[0] = b0.x; bvals[1] = b0.y; bvals[2] = b0.z; bvals[3] = b0.w;
            bvals[4] = b1.x; bvals[5] = b1.y; bvals[6] = b1.z; bvals[7] = b1.w;
#pragma unroll
            for (int j = 0; j < 8; j++) {
                unsigned long long bp;
                asm("mov.b64 %0, {%1, %1};" : "=l"(bp) : "f"(bvals[j]));
#pragma unroll
                for (int i2 = 0; i2 < 4; i2++) {
                    asm("fma.rn.f32x2 %0, %1, %2, %0;"
                        : "+l"(acc[i2][j]) : "l"(ap[i2]), "l"(bp));
                }
            }
        }
        if (more) {
            int nb = buf ^ 1;
            As[nb][aCol + 0][aRow] = av.x;
            As[nb][aCol + 1][aRow] = av.y;
            As[nb][aCol + 2][aRow] = av.z;
            As[nb][aCol + 3][aRow] = av.w;
            if (transB) {
                Bs[nb][aCol + 0][aRow] = bv.x;
                Bs[nb][aCol + 1][aRow] = bv.y;
                Bs[nb][aCol + 2][aRow] = bv.z;
                Bs[nb][aCol + 3][aRow] = bv.w;
            } else {
                *reinterpret_cast<float4*>(&Bs[nb][bRow][bCol]) = bv;
            }
        }
        __syncthreads();
        buf ^= 1;
    }

#pragma unroll
    for (int i2 = 0; i2 < 4; i2++) {
#pragma unroll
        for (int j = 0; j < 8; j++) {
            float lo, hi;
            asm("mov.b64 {%0, %1}, %2;" : "=f"(lo), "=f"(hi) : "l"(acc[i2][j]));
            int c = col0 + tcol + j;
#pragma unroll
            for (int half = 0; half < 2; half++) {
                int r = row0 + trow + 2 * i2 + half;
                float v = (half == 0 ? lo : hi) * scale;
                if (bias) v += bias[c];
                if (residual) v += residual[(long long)r * ldr + c];
                C[(long long)r * ldc + c] = v;
            }
        }
    }
}

// ---------------- RoPE (fp32, fast) ----------------
__global__ void rope_kernel(float* __restrict__ q, float* __restrict__ k) {
    int s = blockIdx.x;
    int h = blockIdx.y;
    int j = threadIdx.x;  // 0..63
    float inv = exp2f(-(float)j * 0.31143075889569023f);
    float ang = (float)s * inv;
    float c, sn;
    sincosf(ang, &sn, &c);
    long long base = ((long long)s * NH + h) * D;
    float q1 = q[base + j], q2 = q[base + j + 64];
    q[base + j] = q1 * c - q2 * sn;
    q[base + j + 64] = q2 * c + q1 * sn;
    float k1 = k[base + j], k2 = k[base + j + 64];
    k[base + j] = k1 * c - k2 * sn;
    k[base + j + 64] = k2 * c + k1 * sn;
}

// ---------------- causal row softmax ----------------
__global__ void softmax_kernel(float* __restrict__ scores) {
    int r = blockIdx.x;
    float* row = scores + ((long long)blockIdx.y * S + r) * S;
    const int limit = r + 1;
    const int rBlk = ((r >> 7) + 1) << 7;
    __shared__ float red[256];
    int tid = threadIdx.x;
    float m = -FLT_MAX;
    for (int j = tid; j < limit; j += 256) m = fmaxf(m, row[j]);
    red[tid] = m;
    __syncthreads();
    for (int st = 128; st > 0; st >>= 1) {
        if (tid < st) red[tid] = fmaxf(red[tid], red[tid + st]);
        __syncthreads();
    }
    m = red[0];
    __syncthreads();
    float sum = 0.f;
    for (int j = tid; j < limit; j += 256) {
        float e = expf(row[j] - m);
        row[j] = e;
        sum += e;
    }
    red[tid] = sum;
    __syncthreads();
    for (int st = 128; st > 0; st >>= 1) {
        if (tid < st) red[tid] += red[tid + st];
        __syncthreads();
    }
    float inv = 1.0f / red[0];
    for (int j = tid; j < limit; j += 256) row[j] *= inv;
    for (int j = limit + tid; j < rBlk; j += 256) row[j] = 0.f;
}

// ---------------- router ----------------
__global__ void router_kernel(const float* __restrict__ h2,
                              const float* __restrict__ gate_w,
                              float* __restrict__ logits_out,
                              int* __restrict__ idxbuf,
                              int* __restrict__ cnt,
                              int* __restrict__ tokmap,
                              float* __restrict__ tokw) {
    int s = blockIdx.x;
    const float* hr = h2 + (long long)s * H;
    __shared__ float red[256][E];
    float p[E];
#pragma unroll
    for (int e = 0; e < E; e++) p[e] = 0.f;
    for (int j = threadIdx.x; j < H; j += 256) {
        float hv = hr[j];
#pragma unroll
        for (int e = 0; e < E; e++) p[e] += hv * gate_w[j * E + e];
    }
#pragma unroll
    for (int e = 0; e < E; e++) red[threadIdx.x][e] = p[e];
    __syncthreads();
    for (int st = 128; st > 0; st >>= 1) {
        if (threadIdx.x < st)
#pragma unroll
            for (int e = 0; e < E; e++) red[threadIdx.x][e] += red[threadIdx.x + st][e];
        __syncthreads();
    }
    if (threadIdx.x == 0) {
        float logit[E];
        float m = -FLT_MAX;
#pragma unroll
        for (int e = 0; e < E; e++) {
            logit[e] = red[0][e];
            logits_out[(long long)s * E + e] = logit[e];
            m = fmaxf(m, logit[e]);
        }
        float sum = 0.f, rw[E];
#pragma unroll
        for (int e = 0; e < E; e++) {
            rw[e] = expf(logit[e] - m);
            sum += rw[e];
        }
        float inv = 1.0f / sum;
#pragma unroll
        for (int e = 0; e < E; e++) rw[e] *= inv;
        bool used[E];
#pragma unroll
        for (int e = 0; e < E; e++) used[e] = false;
        for (int k = 0; k < TOPK; k++) {
            int best = -1;
            float bvv = -FLT_MAX;
            for (int e = 0; e < E; e++)
                if (!used[e] && rw[e] > bvv) { bvv = rw[e]; best = e; }
            used[best] = true;
            int pos = atomicAdd(&cnt[best], 1);
            idxbuf[best * S + pos] = s;
            tokmap[s * TOPK + k] = best * S + pos;
            tokw[s * TOPK + k] = bvv;
        }
    }
}

// ---------------- h2 . sgate ----------------
__global__ void rowdot_kernel(const float* __restrict__ h2,
                              const float* __restrict__ sgate,
                              float* __restrict__ gatev) {
    int s = blockIdx.x;
    const float* hr = h2 + (long long)s * H;
    __shared__ float red[256];
    float acc = 0.f;
    for (int j = threadIdx.x; j < H; j += 256) acc += hr[j] * sgate[j];
    red[threadIdx.x] = acc;
    __syncthreads();
    for (int st = 128; st > 0; st >>= 1) {
        if (threadIdx.x < st) red[threadIdx.x] += red[threadIdx.x + st];
        __syncthreads();
    }
    if (threadIdx.x == 0) gatev[s] = red[0];
}

// ---------------- silu(g)*u, experts (output tf32-rounded) ----------------
__global__ void silu_mul_expert_kernel(float* __restrict__ gb,
                                       const float* __restrict__ ub,
                                       const int* __restrict__ cnt) {
    int e = blockIdx.y;
    long long i = (long long)blockIdx.x * 256 + threadIdx.x;
    long long lim = (long long)cnt[e] * IE;
    if (i >= lim) return;
    size_t o = (size_t)e * S * IE + i;
    float x = gb[o];
    float sg = 1.0f / (1.0f + expf(-x));
    gb[o] = f2tf32f(x * sg * ub[o]);
}

// ---------------- silu(g)*u shared (output tf32-rounded) ----------------
__global__ void silu_mul_kernel(float* __restrict__ g, const float* __restrict__ u,
                                long long n) {
    long long i = (long long)blockIdx.x * 256 + threadIdx.x;
    if (i < n) {
        float x = g[i];
        float sg = 1.0f / (1.0f + expf(-x));
        g[i] = f2tf32f(x * sg * u[i]);
    }
}

// ---------------- final combine ----------------
__global__ void final_kernel(const float* __restrict__ x1,
                             const float* __restrict__ eo,
                             const int* __restrict__ tokmap,
                             const float* __restrict__ tokw,
                             const float* __restrict__ sdwn,
                             const float* __restrict__ gatev,
                             float* __restrict__ out) {
    long long i = (long long)blockIdx.x * 256 + threadIdx.x;
    int s = (int)(i / H);
    int c = (int)(i % H);
    float gv = 1.0f / (1.0f + expf(-gatev[s]));
    float acc = x1[i] + gv * sdwn[i];
#pragma unroll
    for (int j = 0; j < TOPK; j++) {
        int row = tokmap[s * TOPK + j];
        acc += tokw[s * TOPK + j] * eo[(size_t)row * H + c];
    }
    out[i] = acc;
}

// ---------------- host ----------------
static void launch_mma(const float* A, int lda, long long aStrE,
                       const float* B0, const float* B1, int ldb, long long bStrE,
                       float* C0, float* C1, int ldc, long long cStrE,
                       int M, int N, int K,
                       const int* gidx, int gstr, const int* cnt, int eShift,
                       int nz) {
    dim3 grid(N / 128, (M + 127) / 128, nz);
    mma_gemm_kernel<<<grid, 128, MMA_SMEM>>>(A, lda, aStrE, B0, B1, ldb, bStrE,
                                             C0, C1, ldc, cStrE, M, N, K,
                                             gidx, gstr, cnt, eShift);
}

extern "C" void kernel_launch(void* const* d_in, const int* in_sizes, int n_in,
                              void* d_out, int out_size) {
    (void)in_sizes; (void)n_in; (void)out_size;
    const float* x     = (const float*)d_in[0];
    const float* ln1   = (const float*)d_in[1];
    const float* ln2   = (const float*)d_in[2];
    const float* wq    = (const float*)d_in[3];
    const float* bq    = (const float*)d_in[4];
    const float* wk    = (const float*)d_in[5];
    const float* bk    = (const float*)d_in[6];
    const float* wv    = (const float*)d_in[7];
    const float* bv    = (const float*)d_in[8];
    const float* wo    = (const float*)d_in[9];
    const float* gatew = (const float*)d_in[10];
    const float* eg    = (const float*)d_in[11];
    const float* eu    = (const float*)d_in[12];
    const float* ed    = (const float*)d_in[13];
    const float* sg    = (const float*)d_in[14];
    const float* su    = (const float*)d_in[15];
    const float* sd    = (const float*)d_in[16];
    const float* sgate = (const float*)d_in[17];
    float* out = (float*)d_out;

    cudaFuncSetAttribute(mma_gemm_kernel,
                         cudaFuncAttributeMaxDynamicSharedMemorySize, MMA_SMEM);

    float *h, *q, *k, *v, *scores, *attn, *x1, *h2, *ch2, *gb, *ub, *eo, *sgb,
        *sub, *sdwn, *gatev, *tokw;
    float *ceg, *ceu, *ced, *csg, *csu, *csd;
    int *idx, *cnt, *tokmap;
    cudaGetSymbolAddress((void**)&h, g_h);
    cudaGetSymbolAddress((void**)&q, g_q);
    cudaGetSymbolAddress((void**)&k, g_k);
    cudaGetSymbolAddress((void**)&v, g_v);
    cudaGetSymbolAddress((void**)&scores, g_scores);
    cudaGetSymbolAddress((void**)&attn, g_attn);
    cudaGetSymbolAddress((void**)&x1, g_x1);
    cudaGetSymbolAddress((void**)&h2, g_h2);
    cudaGetSymbolAddress((void**)&ch2, g_ch2);
    cudaGetSymbolAddress((void**)&gb, g_gb);
    cudaGetSymbolAddress((void**)&ub, g_ub);
    cudaGetSymbolAddress((void**)&eo, g_eo);
    cudaGetSymbolAddress((void**)&sgb, g_sgb);
    cudaGetSymbolAddress((void**)&sub, g_sub);
    cudaGetSymbolAddress((void**)&sdwn, g_sdwn);
    cudaGetSymbolAddress((void**)&gatev, g_gatev);
    cudaGetSymbolAddress((void**)&idx, g_idx);
    cudaGetSymbolAddress((void**)&cnt, g_cnt);
    cudaGetSymbolAddress((void**)&tokmap, g_tokmap);
    cudaGetSymbolAddress((void**)&tokw, g_tokw);
    cudaGetSymbolAddress((void**)&ceg, g_ceg);
    cudaGetSymbolAddress((void**)&ceu, g_ceu);
    cudaGetSymbolAddress((void**)&ced, g_ced);
    cudaGetSymbolAddress((void**)&csg, g_csg);
    cudaGetSymbolAddress((void**)&csu, g_csu);
    cudaGetSymbolAddress((void**)&csd, g_csd);

    const float ascale = 0.08838834764831845f;

    // 0. pre-round all MoE/shared weights to tf32 in ONE launch
    {
        long long nEG = (long long)E * H * IE / 4;
        long long nED = (long long)E * IE * H / 4;
        long long nSG = (long long)H * IS / 4;
        long long nSD = (long long)IS * H / 4;
        unsigned gx = (unsigned)((nEG + 255) / 256);
        dim3 grid(gx, 6);
        cvt6_kernel<<<grid, 256>>>((const float4*)eg, (float4*)ceg, nEG,
                                   (const float4*)eu, (float4*)ceu, nEG,
                                   (const float4*)ed, (float4*)ced, nED,
                                   (const float4*)sg, (float4*)csg, nSG,
                                   (const float4*)su, (float4*)csu, nSG,
                                   (const float4*)sd, (float4*)csd, nSD);
    }

    // 1. h = rmsnorm(x, ln1)
    rmsnorm_kernel<<<S, 256>>>(x, ln1, h, nullptr);

    // 2. q,k,v (batched fp32)
    {
        dim3 grid((NH * D) / 128, S / 128, 3);
        sgemm_kernel<<<grid, 256>>>(h, H, 0, wq, NH * D, 0, q, NH * D, 0, H,
                                    bq, nullptr, 0, 0, 0, 0, 1.0f,
                                    1, wk, wv, bk, bv, k, v);
    }

    // 3. RoPE
    rope_kernel<<<dim3(S, NH), 64>>>(q, k);

    // 4. scores
    {
        dim3 grid(S / 128, S / 128, NH);
        sgemm_kernel<<<grid, 256>>>(q, NH * D, D, k, NH * D, D, scores, S,
                                    (long long)S * S, D, nullptr, nullptr, 0,
                                    1, 1, 0, ascale,
                                    0, nullptr, nullptr, nullptr, nullptr,
                                    nullptr, nullptr);
    }

    // 5. softmax
    softmax_kernel<<<dim3(S, NH), 256>>>(scores);

    // 6. attn = probs @ v
    {
        dim3 grid(D / 128, S / 128, NH);
        sgemm_kernel<<<grid, 256>>>(scores, S, (long long)S * S, v, NH * D, D,
                                    attn, NH * D, D, S, nullptr, nullptr, 0,
                                    0, 0, 1, 1.0f,
                                    0, nullptr, nullptr, nullptr, nullptr,
                                    nullptr, nullptr);
    }

    // 7. x1 = x + attn @ wo
    {
        dim3 grid(H / 128, S / 128, 1);
        sgemm_kernel<<<grid, 256>>>(attn, NH * D, 0, wo, H, 0, x1, H, 0,
                                    NH * D, nullptr, x, H, 0, 0, 0, 1.0f,
                                    0, nullptr, nullptr, nullptr, nullptr,
                                    nullptr, nullptr);
    }

    // 8. h2 = rmsnorm(x1, ln2) + tf32 copy (fused)
    rmsnorm_kernel<<<S, 256>>>(x1, ln2, h2, ch2);

    // 9. router (exact h2)
    cudaMemsetAsync(cnt, 0, E * sizeof(int));
    router_kernel<<<S, 256>>>(h2, gatew, out + (long long)S * H, idx, cnt,
                              tokmap, tokw);

    // 10. MoE gate+up (z = 2E)
    launch_mma(ch2, H, 0, ceg, ceu, IE, (long long)H * IE,
               gb, ub, IE, (long long)S * IE, S, IE, H, idx, S, cnt, 1, 2 * E);

    // 11. silu (+tf32 round)
    {
        dim3 grid((unsigned)(((long long)S * IE + 255) / 256), E);
        silu_mul_expert_kernel<<<grid, 256>>>(gb, ub, cnt);
    }

    // 12. MoE down (z = E)
    launch_mma(gb, IE, (long long)S * IE, ced, nullptr, H, (long long)IE * H,
               eo, nullptr, H, (long long)S * H, S, H, IE, nullptr, 0, cnt, 0, E);

    // 13. shared expert
    launch_mma(ch2, H, 0, csg, csu, IS, 0, sgb, sub, IS, 0, S, IS, H,
               nullptr, 0, nullptr, 1, 2);
    {
        long long n = (long long)S * IS;
        silu_mul_kernel<<<(unsigned)((n + 255) / 256), 256>>>(sgb, sub, n);
    }
    launch_mma(sgb, IS, 0, csd, nullptr, H, 0, sdwn, nullptr, H, 0, S, H, IS,
               nullptr, 0, nullptr, 0, 1);

    // 14. gate scalar
    rowdot_kernel<<<S, 256>>>(h2, sgate, gatev);

    // 15. combine
    final_kernel<<<(S * H) / 256, 256>>>(x1, eo, tokmap, tokw, sdwn, gatev, out);
}

// round 10
// speedup vs baseline: 1.1522x; 1.0589x over previous
#include <cuda_runtime.h>
#include <cuda_bf16.h>
#include <math.h>
#include <float.h>
#include <stdint.h>

#define S 2048
#define H 2048
#define NH 16
#define D 128
#define E 8
#define TOPK 4
#define IE 1408
#define IS 5632

// ---------------- scratch (static device globals; no allocation) --------------
__device__ float g_hhi[S * H];
__device__ float g_hlo[S * H];
__device__ float g_q[S * H];
__device__ float g_k[S * H];
__device__ float g_v[S * H];
__device__ float g_scores[(size_t)NH * S * S];
__device__ float g_attn[S * H];
__device__ float g_ahi[S * H];
__device__ float g_alo[S * H];
__device__ float g_x1[S * H];
__device__ float g_h2[S * H];
__device__ float g_ch2[S * H];
__device__ float g_gb[(size_t)E * S * IE];
__device__ float g_ub[(size_t)E * S * IE];
__device__ float g_eo[(size_t)E * S * H];
__device__ float g_sgb[S * IS];
__device__ float g_sub[S * IS];
__device__ float g_sdwn[S * H];
__device__ float g_gatev[S];
__device__ int g_idx[E * S];
__device__ int g_cnt[E];
__device__ int g_tokmap[S * TOPK];
__device__ float g_tokw[S * TOPK];
// tf32-preconverted MoE weights
__device__ float g_ceg[(size_t)E * H * IE];
__device__ float g_ceu[(size_t)E * H * IE];
__device__ float g_ced[(size_t)E * IE * H];
__device__ float g_csg[(size_t)H * IS];
__device__ float g_csu[(size_t)H * IS];
__device__ float g_csd[(size_t)IS * H];
// hi/lo splits of attention weights: [wqh,wql,wkh,wkl,wvh,wvl,woh,wol]
__device__ float g_wsp[(size_t)8 * H * H];

// ================= helpers =================
__device__ __forceinline__ uint32_t smem_to_u32(const void* p) {
    uint32_t a;
    asm("{ .reg .u64 t; cvta.to.shared.u64 t, %1; cvt.u32.u64 %0, t; }"
        : "=r"(a) : "l"(p));
    return a;
}
__device__ __forceinline__ float f2tf32f(float f) {
    uint32_t r;
    asm("cvt.rna.tf32.f32 %0, %1;" : "=r"(r) : "f"(f));
    return __uint_as_float(r);
}
__device__ __forceinline__ void mma_tf32(float* d, const uint32_t* a,
                                         const uint32_t* b) {
    asm volatile(
        "mma.sync.aligned.m16n8k8.row.col.f32.tf32.tf32.f32 "
        "{%0,%1,%2,%3}, {%4,%5,%6,%7}, {%8,%9}, {%0,%1,%2,%3};"
        : "+f"(d[0]), "+f"(d[1]), "+f"(d[2]), "+f"(d[3])
        : "r"(a[0]), "r"(a[1]), "r"(a[2]), "r"(a[3]), "r"(b[0]), "r"(b[1]));
}
__device__ __forceinline__ void cp_async16(uint32_t dst, const void* src) {
    asm volatile("cp.async.ca.shared.global [%0], [%1], 16;"
                 :: "r"(dst), "l"(src));
}

// ================= tf32 mma GEMM v3 (MoE path, unchanged) =====================
#define APADF 20
#define BPADF 136
#define A_STAGE_B (128 * APADF * 4)  // 10240
#define B_STAGE_B (16 * BPADF * 4)   // 8704
#define STAGE_B (A_STAGE_B + B_STAGE_B)
#define NSTAGE 4
#define MMA_SMEM (STAGE_B * NSTAGE)  // 75776

__global__ __launch_bounds__(128, 2)
void mma_gemm_kernel(const float* __restrict__ A, int lda, long long aStrE,
                     const float* __restrict__ B0, const float* __restrict__ B1,
                     int ldb, long long bStrE,
                     float* __restrict__ C0, float* __restrict__ C1,
                     int ldc, long long cStrE,
                     int M, int N, int K,
                     const int* __restrict__ gidxBase, int gidxStr,
                     const int* __restrict__ cntBase, int eShift) {
    extern __shared__ char smem[];
    const uint32_t sb = smem_to_u32(smem);
    const int z = blockIdx.z;
    const int e = z >> eShift;
    const int which = z & ((1 << eShift) - 1);
    const float* B = (which ? B1 : B0) + (long long)e * bStrE;
    float* C = (which ? C1 : C0) + (long long)e * cStrE;
    A += (long long)e * aStrE;

    const int cnt = cntBase ? cntBase[e] : M;
    const int mEff = min(M, cnt);
    const int row0 = blockIdx.y * 128;
    const int col0 = blockIdx.x * 128;
    if (row0 >= mEff) return;
    const int* gidx = gidxBase ? gidxBase + (long long)e * gidxStr : nullptr;

    const int tid = threadIdx.x;
    const int wid = tid >> 5;
    const int lane = tid & 31;
    const int g = lane >> 2;
    const int t4 = lane & 3;
    const int warpM = wid >> 1;
    const int warpN = wid & 1;

    const float* aG[4];
    uint32_t aS[4];
#pragma unroll
    for (int j = 0; j < 4; j++) {
        int u = tid + 128 * j;
        int m = u >> 2, c4 = u & 3;
        int arow = row0 + m;
        int src;
        if (gidx) src = (arow < cnt) ? gidx[arow] : 0;
        else src = min(arow, M - 1);
        aG[j] = A + (size_t)src * lda + c4 * 4;
        aS[j] = sb + (uint32_t)(m * APADF + c4 * 4) * 4u;
    }
    const float* bG[4];
    uint32_t bS[4];
#pragma unroll
    for (int j = 0; j < 4; j++) {
        int u = tid + 128 * j;
        int n4 = u & 31, kk = u >> 5;
        bG[j] = B + (size_t)kk * ldb + col0 + n4 * 4;
        bS[j] = sb + A_STAGE_B + (uint32_t)(kk * BPADF + n4 * 4) * 4u;
    }

    float acc[4][8][4];
#pragma unroll
    for (int mt = 0; mt < 4; mt++)
#pragma unroll
        for (int nt = 0; nt < 8; nt++)
#pragma unroll
            for (int r = 0; r < 4; r++) acc[mt][nt][r] = 0.f;

    const int nT = K / 16;

#define ISSUE(i)                                                      \
    do {                                                              \
        uint32_t _off = (uint32_t)((i) & 3) * STAGE_B;                \
        int _k0 = (i) * 16;                                           \
        cp_async16(aS[0] + _off, aG[0] + _k0);                        \
        cp_async16(aS[1] + _off, aG[1] + _k0);                        \
        cp_async16(aS[2] + _off, aG[2] + _k0);                        \
        cp_async16(aS[3] + _off, aG[3] + _k0);                        \
        cp_async16(bS[0] + _off, bG[0] + (size_t)_k0 * ldb);          \
        cp_async16(bS[1] + _off, bG[1] + (size_t)_k0 * ldb);          \
        cp_async16(bS[2] + _off, bG[2] + (size_t)_k0 * ldb);          \
        cp_async16(bS[3] + _off, bG[3] + (size_t)_k0 * ldb);          \
        asm volatile("cp.async.commit_group;");                       \
    } while (0)

    ISSUE(0);
    if (nT > 1) ISSUE(1);
    if (nT > 2) ISSUE(2);

    for (int i = 0; i < nT; i++) {
        const int rem = nT - 1 - i;
        if (rem >= 2)
            asm volatile("cp.async.wait_group 2;");
        else if (rem == 1)
            asm volatile("cp.async.wait_group 1;");
        else
            asm volatile("cp.async.wait_group 0;");
        __syncthreads();
        if (i + 3 < nT) ISSUE(i + 3);

        const uint32_t* Asb =
            (const uint32_t*)(smem + (size_t)(i & 3) * STAGE_B);
        const uint32_t* Bsb =
            (const uint32_t*)(smem + (size_t)(i & 3) * STAGE_B + A_STAGE_B);
#pragma unroll
        for (int kk = 0; kk < 16; kk += 8) {
            uint32_t a[4][4], b[8][2];
#pragma unroll
            for (int mt = 0; mt < 4; mt++) {
                int mrow = warpM * 64 + mt * 16;
                a[mt][0] = Asb[(mrow + g) * APADF + kk + t4];
                a[mt][1] = Asb[(mrow + g + 8) * APADF + kk + t4];
                a[mt][2] = Asb[(mrow + g) * APADF + kk + t4 + 4];
                a[mt][3] = Asb[(mrow + g + 8) * APADF + kk + t4 + 4];
            }
#pragma unroll
            for (int nt = 0; nt < 8; nt++) {
                int ncol = warpN * 64 + nt * 8;
                b[nt][0] = Bsb[(kk + t4) * BPADF + ncol + g];
                b[nt][1] = Bsb[(kk + t4 + 4) * BPADF + ncol + g];
            }
#pragma unroll
            for (int mt = 0; mt < 4; mt++)
#pragma unroll
                for (int nt = 0; nt < 8; nt++)
                    mma_tf32(acc[mt][nt], a[mt], b[nt]);
        }
    }
#undef ISSUE

#pragma unroll
    for (int mt = 0; mt < 4; mt++) {
        int rBase = row0 + warpM * 64 + mt * 16 + g;
#pragma unroll
        for (int half = 0; half < 2; half++) {
            int r = rBase + half * 8;
            if (r >= mEff) continue;
            float* cp = C + (size_t)r * ldc;
#pragma unroll
            for (int nt = 0; nt < 8; nt++) {
                int col = col0 + warpN * 64 + nt * 8 + t4 * 2;
                cp[col] = acc[mt][nt][half * 2 + 0];
                cp[col + 1] = acc[mt][nt][half * 2 + 1];
            }
        }
    }
}

// ================= 3xTF32 mma GEMM (fp32-accurate, pre-router path) ==========
// C = (Ahi+Alo)@(Bhi+Blo) dropping lo*lo. CTA 128x128, 4 warps @64x64,
// K-tile 8, 4-stage cp.async ring, 2 CTA/SM. z selects among 3 (B,bias,C).
#define X_APAD 12
#define X_BPAD 136
#define X_A_B (128 * X_APAD * 4)  // 6144
#define X_B_B (8 * X_BPAD * 4)    // 4352
#define X_STAGE (2 * X_A_B + 2 * X_B_B)  // 20992
#define X_SMEM (X_STAGE * 4)             // 83968

__global__ __launch_bounds__(128, 2)
void mma3x_kernel(const float* __restrict__ Ahi, const float* __restrict__ Alo,
                  int lda,
                  const float* __restrict__ B0h, const float* __restrict__ B0l,
                  const float* __restrict__ B1h, const float* __restrict__ B1l,
                  const float* __restrict__ B2h, const float* __restrict__ B2l,
                  int ldb,
                  const float* __restrict__ bias0,
                  const float* __restrict__ bias1,
                  const float* __restrict__ bias2,
                  float* __restrict__ C0, float* __restrict__ C1,
                  float* __restrict__ C2, int ldc,
                  const float* __restrict__ residual,
                  int K) {
    extern __shared__ char smem[];
    const uint32_t sb = smem_to_u32(smem);
    const int z = blockIdx.z;
    const float* Bh = (z == 0) ? B0h : (z == 1 ? B1h : B2h);
    const float* Bl = (z == 0) ? B0l : (z == 1 ? B1l : B2l);
    const float* bias = (z == 0) ? bias0 : (z == 1 ? bias1 : bias2);
    float* C = (z == 0) ? C0 : (z == 1 ? C1 : C2);

    const int row0 = blockIdx.y * 128;
    const int col0 = blockIdx.x * 128;

    const int tid = threadIdx.x;
    const int wid = tid >> 5;
    const int lane = tid & 31;
    const int g = lane >> 2;
    const int t4 = lane & 3;
    const int warpM = wid >> 1;
    const int warpN = wid & 1;

    const long long aLoD = Alo - Ahi;
    const long long bLoD = Bl - Bh;

    // A: 2 f4-tasks: u = tid + 128*j : m = u>>1, c4 = u&1
    const float* aGh[2];
    uint32_t aSh[2];
#pragma unroll
    for (int j = 0; j < 2; j++) {
        int u = tid + 128 * j;
        int m = u >> 1, c4 = u & 1;
        aGh[j] = Ahi + (size_t)(row0 + m) * lda + c4 * 4;
        aSh[j] = sb + (uint32_t)(m * X_APAD + c4 * 4) * 4u;
    }
    // B: 2 f4-tasks: u = tid + 128*j : kk = u>>5, n4 = u&31
    const float* bGh[2];
    uint32_t bSh[2];
#pragma unroll
    for (int j = 0; j < 2; j++) {
        int u = tid + 128 * j;
        int kk = u >> 5, n4 = u & 31;
        bGh[j] = Bh + (size_t)kk * ldb + col0 + n4 * 4;
        bSh[j] = sb + (uint32_t)(2 * X_A_B) +
                 (uint32_t)(kk * X_BPAD + n4 * 4) * 4u;
    }

    float acc[4][8][4];
#pragma unroll
    for (int mt = 0; mt < 4; mt++)
#pragma unroll
        for (int nt = 0; nt < 8; nt++)
#pragma unroll
            for (int r = 0; r < 4; r++) acc[mt][nt][r] = 0.f;

    const int nT = K / 8;

#define XISSUE(i)                                                       \
    do {                                                                \
        uint32_t _off = (uint32_t)((i) & 3) * X_STAGE;                  \
        int _k0 = (i) * 8;                                              \
        cp_async16(aSh[0] + _off, aGh[0] + _k0);                        \
        cp_async16(aSh[1] + _off, aGh[1] + _k0);                        \
        cp_async16(aSh[0] + X_A_B + _off, aGh[0] + aLoD + _k0);         \
        cp_async16(aSh[1] + X_A_B + _off, aGh[1] + aLoD + _k0);         \
        cp_async16(bSh[0] + _off, bGh[0] + (size_t)_k0 * ldb);          \
        cp_async16(bSh[1] + _off, bGh[1] + (size_t)_k0 * ldb);          \
        cp_async16(bSh[0] + X_B_B + _off, bGh[0] + bLoD + (size_t)_k0 * ldb); \
        cp_async16(bSh[1] + X_B_B + _off, bGh[1] + bLoD + (size_t)_k0 * ldb); \
        asm volatile("cp.async.commit_group;");                         \
    } while (0)

    XISSUE(0);
    XISSUE(1);
    XISSUE(2);

    for (int i = 0; i < nT; i++) {
        const int rem = nT - 1 - i;
        if (rem >= 2)
            asm volatile("cp.async.wait_group 2;");
        else if (rem == 1)
            asm volatile("cp.async.wait_group 1;");
        else
            asm volatile("cp.async.wait_group 0;");
        __syncthreads();
        if (i + 3 < nT) XISSUE(i + 3);

        const uint32_t* Ah = (const uint32_t*)(smem + (size_t)(i & 3) * X_STAGE);
        const uint32_t* Al = Ah + (X_A_B / 4);
        const uint32_t* Bhs =
            (const uint32_t*)(smem + (size_t)(i & 3) * X_STAGE + 2 * X_A_B);
        const uint32_t* Bls = Bhs + (X_B_B / 4);

        uint32_t ah[4][4], al[4][4], bh[8][2], bl[8][2];
#pragma unroll
        for (int mt = 0; mt < 4; mt++) {
            int mrow = warpM * 64 + mt * 16;
            ah[mt][0] = Ah[(mrow + g) * X_APAD + t4];
            ah[mt][1] = Ah[(mrow + g + 8) * X_APAD + t4];
            ah[mt][2] = Ah[(mrow + g) * X_APAD + t4 + 4];
            ah[mt][3] = Ah[(mrow + g + 8) * X_APAD + t4 + 4];
            al[mt][0] = Al[(mrow + g) * X_APAD + t4];
            al[mt][1] = Al[(mrow + g + 8) * X_APAD + t4];
            al[mt][2] = Al[(mrow + g) * X_APAD + t4 + 4];
            al[mt][3] = Al[(mrow + g + 8) * X_APAD + t4 + 4];
        }
#pragma unroll
        for (int nt = 0; nt < 8; nt++) {
            int ncol = warpN * 64 + nt * 8;
            bh[nt][0] = Bhs[t4 * X_BPAD + ncol + g];
            bh[nt][1] = Bhs[(t4 + 4) * X_BPAD + ncol + g];
            bl[nt][0] = Bls[t4 * X_BPAD + ncol + g];
            bl[nt][1] = Bls[(t4 + 4) * X_BPAD + ncol + g];
        }
#pragma unroll
        for (int mt = 0; mt < 4; mt++)
#pragma unroll
            for (int nt = 0; nt < 8; nt++) {
                mma_tf32(acc[mt][nt], ah[mt], bh[nt]);
                mma_tf32(acc[mt][nt], ah[mt], bl[nt]);
                mma_tf32(acc[mt][nt], al[mt], bh[nt]);
            }
    }
#undef XISSUE

    // epilogue
#pragma unroll
    for (int mt = 0; mt < 4; mt++) {
        int rBase = row0 + warpM * 64 + mt * 16 + g;
#pragma unroll
        for (int half = 0; half < 2; half++) {
            int r = rBase + half * 8;
            float* cp = C + (size_t)r * ldc;
            const float* rp = residual ? residual + (size_t)r * ldc : nullptr;
#pragma unroll
            for (int nt = 0; nt < 8; nt++) {
                int col = col0 + warpN * 64 + nt * 8 + t4 * 2;
                float v0 = acc[mt][nt][half * 2 + 0];
                float v1 = acc[mt][nt][half * 2 + 1];
                if (bias) {
                    v0 += bias[col];
                    v1 += bias[col + 1];
                }
                if (rp) {
                    v0 += rp[col];
                    v1 += rp[col + 1];
                }
                cp[col] = v0;
                cp[col + 1] = v1;
            }
        }
    }
}

// ---------------- bulk tf32 rounding: 6 MoE weight tensors ----------------
__global__ void cvt6_kernel(const float4* s0, float4* d0, long long n0,
                            const float4* s1, float4* d1, long long n1,
                            const float4* s2, float4* d2, long long n2,
                            const float4* s3, float4* d3, long long n3,
                            const float4* s4, float4* d4, long long n4c,
                            const float4* s5, float4* d5, long long n5) {
    const float4* src;
    float4* dst;
    long long n;
    switch (blockIdx.y) {
        case 0: src = s0; dst = d0; n = n0; break;
        case 1: src = s1; dst = d1; n = n1; break;
        case 2: src = s2; dst = d2; n = n2; break;
        case 3: src = s3; dst = d3; n = n3; break;
        case 4: src = s4; dst = d4; n = n4c; break;
        default: src = s5; dst = d5; n = n5; break;
    }
    long long i = (long long)blockIdx.x * 256 + threadIdx.x;
    if (i < n) {
        float4 v = src[i];
        v.x = f2tf32f(v.x);
        v.y = f2tf32f(v.y);
        v.z = f2tf32f(v.z);
        v.w = f2tf32f(v.w);
        dst[i] = v;
    }
}

// ---------------- hi/lo split of 4 attention weight tensors ----------------
__global__ void split4_kernel(const float4* s0, const float4* s1,
                              const float4* s2, const float4* s3,
                              float4* base) {
    const float4* src = (blockIdx.y == 0) ? s0
                        : (blockIdx.y == 1) ? s1
                        : (blockIdx.y == 2) ? s2 : s3;
    const size_t n4 = (size_t)H * H / 4;
    float4* hi = base + (size_t)(2 * blockIdx.y) * n4;
    float4* lo = hi + n4;
    size_t i = (size_t)blockIdx.x * 256 + threadIdx.x;
    if (i < n4) {
        float4 v = src[i];
        float4 hv, lv;
        hv.x = f2tf32f(v.x); lv.x = f2tf32f(v.x - hv.x);
        hv.y = f2tf32f(v.y); lv.y = f2tf32f(v.y - hv.y);
        hv.z = f2tf32f(v.z); lv.z = f2tf32f(v.z - hv.z);
        hv.w = f2tf32f(v.w); lv.w = f2tf32f(v.w - hv.w);
        hi[i] = hv;
        lo[i] = lv;
    }
}

// ---------------- hi/lo split of one tensor ----------------
__global__ void split1_kernel(const float4* __restrict__ src,
                              float4* __restrict__ hi,
                              float4* __restrict__ lo, long long n4) {
    long long i = (long long)blockIdx.x * 256 + threadIdx.x;
    if (i < n4) {
        float4 v = src[i];
        float4 hv, lv;
        hv.x = f2tf32f(v.x); lv.x = f2tf32f(v.x - hv.x);
        hv.y = f2tf32f(v.y); lv.y = f2tf32f(v.y - hv.y);
        hv.z = f2tf32f(v.z); lv.z = f2tf32f(v.z - hv.z);
        hv.w = f2tf32f(v.w); lv.w = f2tf32f(v.w - hv.w);
        hi[i] = hv;
        lo[i] = lv;
    }
}

// ---------------- RMSNorm: plain / +tf32 copy / hi+lo split ----------------
__global__ void rmsnorm_kernel(const float* __restrict__ x,
                               const float* __restrict__ w,
                               float* __restrict__ out,
                               float* __restrict__ outTf,
                               float* __restrict__ outLo) {
    const float* xr = x + (long long)blockIdx.x * H;
    float* orow = out + (long long)blockIdx.x * H;
    __shared__ float red[256];
    float s = 0.f;
    for (int j = threadIdx.x; j < H; j += 256) {
        float v = xr[j];
        s += v * v;
    }
    red[threadIdx.x] = s;
    __syncthreads();
    for (int st = 128; st > 0; st >>= 1) {
        if (threadIdx.x < st) red[threadIdx.x] += red[threadIdx.x + st];
        __syncthreads();
    }
    float inv = 1.0f / sqrtf(red[0] / (float)H + 1e-6f);
    if (outLo) {
        float* lrow = outLo + (long long)blockIdx.x * H;
        for (int j = threadIdx.x; j < H; j += 256) {
            float v = w[j] * xr[j] * inv;
            float hi = f2tf32f(v);
            orow[j] = hi;
            lrow[j] = f2tf32f(v - hi);
        }
    } else if (outTf) {
        float* trow = outTf + (long long)blockIdx.x * H;
        for (int j = threadIdx.x; j < H; j += 256) {
            float v = w[j] * xr[j] * inv;
            orow[j] = v;
            trow[j] = f2tf32f(v);
        }
    } else {
        for (int j = threadIdx.x; j < H; j += 256) orow[j] = w[j] * xr[j] * inv;
    }
}

// ---------------- fp32 SGEMM (scores / PV) ----------------
__global__ __launch_bounds__(256, 2)
void sgemm_kernel(const float* __restrict__ A, int lda, long long sA,
                  const float* __restrict__ B, int ldb, long long sB,
                  float* __restrict__ C, int ldc, long long sC,
                  int K,
                  const float* __restrict__ bias,
                  const float* __restrict__ residual, int ldr,
                  int transB, int causal, int kLimit, float scale) {
    __shared__ __align__(16) float As[2][8][128];
    __shared__ __align__(16) float Bs[2][8][128];

    const int bz = blockIdx.z;
    A += (long long)bz * sA;
    B += (long long)bz * sB;
    C += (long long)bz * sC;

    const int row0 = blockIdx.y * 128;
    const int col0 = blockIdx.x * 128;
    if (causal && col0 > row0) return;
    int Keff = kLimit ? min(K, row0 + 128) : K;

    const int tid = threadIdx.x;
    const int trow = (tid >> 4) * 8;
    const int tcol = (tid & 15) * 8;

    const int aRow = tid >> 1;
    const int aCol = (tid & 1) * 4;
    const int bRow = tid >> 5;
    const int bCol = (tid & 31) * 4;

    const float* Aptr = A + (long long)(row0 + aRow) * lda + aCol;
    const float* BptrNN = B + (long long)bRow * ldb + col0 + bCol;
    const float* BptrNT = B + (long long)(col0 + aRow) * ldb + aCol;

    unsigned long long acc[4][8];
#pragma unroll
    for (int i = 0; i < 4; i++)
#pragma unroll
        for (int j = 0; j < 8; j++) acc[i][j] = 0ull;

    float4 av = *reinterpret_cast<const float4*>(Aptr);
    float4 bv = transB ? *reinterpret_cast<const float4*>(BptrNT)
                       : *reinterpret_cast<const float4*>(BptrNN);
    As[0][aCol + 0][aRow] = av.x;
    As[0][aCol + 1][aRow] = av.y;
    As[0][aCol + 2][aRow] = av.z;
    As[0][aCol + 3][aRow] = av.w;
    if (transB) {
        Bs[0][aCol + 0][aRow] = bv.x;
        Bs[0][aCol + 1][aRow] = bv.y;
        Bs[0][aCol + 2][aRow] = bv.z;
        Bs[0][aCol + 3][aRow] = bv.w;
    } else {
        *reinterpret_cast<float4*>(&Bs[0][bRow][bCol]) = bv;
    }
    __syncthreads();

    int buf = 0;
    for (int k0 = 0; k0 < Keff; k0 += 8) {
        const bool more = (k0 + 8) < Keff;
        if (more) {
            av = *reinterpret_cast<const float4*>(Aptr + k0 + 8);
            bv = transB
                     ? *reinterpret_cast<const float4*>(BptrNT + k0 + 8)
                     : *reinterpret_cast<const float4*>(BptrNN + (long long)(k0 + 8) * ldb);
        }
#pragma unroll
        for (int kk = 0; kk < 8; kk++) {
            ulonglong2 a01 = *reinterpret_cast<const ulonglong2*>(&As[buf][kk][trow]);
            ulonglong2 a23 = *reinterpret_cast<const ulonglong2*>(&As[buf][kk][trow + 4]);
            float4 b0 = *reinterpret_cast<const float4*>(&Bs[buf][kk][tcol]);
            float4 b1 = *reinterpret_cast<const float4*>(&Bs[buf][kk][tcol + 4]);
            unsigned long long ap[4];
            ap[0] = a01.x; ap[1] = a01.y; ap[2] = a23.x; ap[3] = a23.y;
            float bvals[8];
            bvals[0] = b0.x; bvals[1] = b0.y; bvals[2] = b0.z; bvals[3] = b0.w;
            bvals[4] = b1.x; bvals[5] = b1.y; bvals[6] = b1.z; bvals[7] = b1.w;
#pragma unroll
            for (int j = 0; j < 8; j++) {
                unsigned long long bp;
                asm("mov.b64 %0, {%1, %1};" : "=l"(bp) : "f"(bvals[j]));
#pragma unroll
                for (int i2 = 0; i2 < 4; i2++) {
                    asm("fma.rn.f32x2 %0, %1, %2, %0;"
                        : "+l"(acc[i2][j]) : "l"(ap[i2]), "l"(bp));
                }
            }
        }
        if (more) {
            int nb = buf ^ 1;
            As[nb][aCol + 0][aRow] = av.x;
            As[nb][aCol + 1][aRow] = av.y;
            As[nb][aCol + 2][aRow] = av.z;
            As[nb][aCol + 3][aRow] = av.w;
            if (transB) {
                Bs[nb][aCol + 0][aRow] = bv.x;
                Bs[nb][aCol + 1][aRow] = bv.y;
                Bs[nb][aCol + 2][aRow] = bv.z;
                Bs[nb][aCol + 3][aRow] = bv.w;
            } else {
                *reinterpret_cast<float4*>(&Bs[nb][bRow][bCol]) = bv;
            }
        }
        __syncthreads();
        buf ^= 1;
    }

#pragma unroll
    for (int i2 = 0; i2 < 4; i2++) {
#pragma unroll
        for (int j = 0; j < 8; j++) {
            float lo, hi;
            asm("mov.b64 {%0, %1}, %2;" : "=f"(lo), "=f"(hi) : "l"(acc[i2][j]));
            int c = col0 + tcol + j;
#pragma unroll
            for (int half = 0; half < 2; half++) {
                int r = row0 + trow + 2 * i2 + half;
                float v = (half == 0 ? lo : hi) * scale;
                if (bias) v += bias[c];
                if (residual) v += residual[(long long)r * ldr + c];
                C[(long long)r * ldc + c] = v;
            }
        }
    }
}

// ---------------- RoPE (fp32, fast) ----------------
__global__ void rope_kernel(float* __restrict__ q, float* __restrict__ k) {
    int s = blockIdx.x;
    int h = blockIdx.y;
    int j = threadIdx.x;
    float inv = exp2f(-(float)j * 0.31143075889569023f);
    float ang = (float)s * inv;
    float c, sn;
    sincosf(ang, &sn, &c);
    long long base = ((long long)s * NH + h) * D;
    float q1 = q[base + j], q2 = q[base + j + 64];
    q[base + j] = q1 * c - q2 * sn;
    q[base + j + 64] = q2 * c + q1 * sn;
    float k1 = k[base + j], k2 = k[base + j + 64];
    k[base + j] = k1 * c - k2 * sn;
    k[base + j + 64] = k2 * c + k1 * sn;
}

// ---------------- causal row softmax ----------------
__global__ void softmax_kernel(float* __restrict__ scores) {
    int r = blockIdx.x;
    float* row = scores + ((long long)blockIdx.y * S + r) * S;
    const int limit = r + 1;
    const int rBlk = ((r >> 7) + 1) << 7;
    __shared__ float red[256];
    int tid = threadIdx.x;
    float m = -FLT_MAX;
    for (int j = tid; j < limit; j += 256) m = fmaxf(m, row[j]);
    red[tid] = m;
    __syncthreads();
    for (int st = 128; st > 0; st >>= 1) {
        if (tid < st) red[tid] = fmaxf(red[tid], red[tid + st]);
        __syncthreads();
    }
    m = red[0];
    __syncthreads();
    float sum = 0.f;
    for (int j = tid; j < limit; j += 256) {
        float e = expf(row[j] - m);
        row[j] = e;
        sum += e;
    }
    red[tid] = sum;
    __syncthreads();
    for (int st = 128; st > 0; st >>= 1) {
        if (tid < st) red[tid] += red[tid + st];
        __syncthreads();
    }
    float inv = 1.0f / red[0];
    for (int j = tid; j < limit; j += 256) row[j] *= inv;
    for (int j = limit + tid; j < rBlk; j += 256) row[j] = 0.f;
}

// ---------------- router ----------------
__global__ void router_kernel(const float* __restrict__ h2,
                              const float* __restrict__ gate_w,
                              float* __restrict__ logits_out,
                              int* __restrict__ idxbuf,
                              int* __restrict__ cnt,
                              int* __restrict__ tokmap,
                              float* __restrict__ tokw) {
    int s = blockIdx.x;
    const float* hr = h2 + (long long)s * H;
    __shared__ float red[256][E];
    float p[E];
#pragma unroll
    for (int e = 0; e < E; e++) p[e] = 0.f;
    for (int j = threadIdx.x; j < H; j += 256) {
        float hv = hr[j];
#pragma unroll
        for (int e = 0; e < E; e++) p[e] += hv * gate_w[j * E + e];
    }
#pragma unroll
    for (int e = 0; e < E; e++) red[threadIdx.x][e] = p[e];
    __syncthreads();
    for (int st = 128; st > 0; st >>= 1) {
        if (threadIdx.x < st)
#pragma unroll
            for (int e = 0; e < E; e++) red[threadIdx.x][e] += red[threadIdx.x + st][e];
        __syncthreads();
    }
    if (threadIdx.x == 0) {
        float logit[E];
        float m = -FLT_MAX;
#pragma unroll
        for (int e = 0; e < E; e++) {
            logit[e] = red[0][e];
            logits_out[(long long)s * E + e] = logit[e];
            m = fmaxf(m, logit[e]);
        }
        float sum = 0.f, rw[E];
#pragma unroll
        for (int e = 0; e < E; e++) {
            rw[e] = expf(logit[e] - m);
            sum += rw[e];
        }
        float inv = 1.0f / sum;
#pragma unroll
        for (int e = 0; e < E; e++) rw[e] *= inv;
        bool used[E];
#pragma unroll
        for (int e = 0; e < E; e++) used[e] = false;
        for (int k = 0; k < TOPK; k++) {
            int best = -1;
            float bvv = -FLT_MAX;
            for (int e = 0; e < E; e++)
                if (!used[e] && rw[e] > bvv) { bvv = rw[e]; best = e; }
            used[best] = true;
            int pos = atomicAdd(&cnt[best], 1);
            idxbuf[best * S + pos] = s;
            tokmap[s * TOPK + k] = best * S + pos;
            tokw[s * TOPK + k] = bvv;
        }
    }
}

// ---------------- h2 . sgate ----------------
__global__ void rowdot_kernel(const float* __restrict__ h2,
                              const float* __restrict__ sgate,
                              float* __restrict__ gatev) {
    int s = blockIdx.x;
    const float* hr = h2 + (long long)s * H;
    __shared__ float red[256];
    float acc = 0.f;
    for (int j = threadIdx.x; j < H; j += 256) acc += hr[j] * sgate[j];
    red[threadIdx.x] = acc;
    __syncthreads();
    for (int st = 128; st > 0; st >>= 1) {
        if (threadIdx.x < st) red[threadIdx.x] += red[threadIdx.x + st];
        __syncthreads();
    }
    if (threadIdx.x == 0) gatev[s] = red[0];
}

// ---------------- silu(g)*u, experts (output tf32-rounded) ----------------
__global__ void silu_mul_expert_kernel(float* __restrict__ gb,
                                       const float* __restrict__ ub,
                                       const int* __restrict__ cnt) {
    int e = blockIdx.y;
    long long i = (long long)blockIdx.x * 256 + threadIdx.x;
    long long lim = (long long)cnt[e] * IE;
    if (i >= lim) return;
    size_t o = (size_t)e * S * IE + i;
    float x = gb[o];
    float sg = 1.0f / (1.0f + expf(-x));
    gb[o] = f2tf32f(x * sg * ub[o]);
}

// ---------------- silu(g)*u shared (output tf32-rounded) ----------------
__global__ void silu_mul_kernel(float* __restrict__ g, const float* __restrict__ u,
                                long long n) {
    long long i = (long long)blockIdx.x * 256 + threadIdx.x;
    if (i < n) {
        float x = g[i];
        float sg = 1.0f / (1.0f + expf(-x));
        g[i] = f2tf32f(x * sg * u[i]);
    }
}

// ---------------- final combine ----------------
__global__ void final_kernel(const float* __restrict__ x1,
                             const float* __restrict__ eo,
                             const int* __restrict__ tokmap,
                             const float* __restrict__ tokw,
                             const float* __restrict__ sdwn,
                             const float* __restrict__ gatev,
                             float* __restrict__ out) {
    long long i = (long long)blockIdx.x * 256 + threadIdx.x;
    int s = (int)(i / H);
    int c = (int)(i % H);
    float gv = 1.0f / (1.0f + expf(-gatev[s]));
    float acc = x1[i] + gv * sdwn[i];
#pragma unroll
    for (int j = 0; j < TOPK; j++) {
        int row = tokmap[s * TOPK + j];
        acc += tokw[s * TOPK + j] * eo[(size_t)row * H + c];
    }
    out[i] = acc;
}

// ---------------- host ----------------
static void launch_mma(const float* A, int lda, long long aStrE,
                       const float* B0, const float* B1, int ldb, long long bStrE,
                       float* C0, float* C1, int ldc, long long cStrE,
                       int M, int N, int K,
                       const int* gidx, int gstr, const int* cnt, int eShift,
                       int nz) {
    dim3 grid(N / 128, (M + 127) / 128, nz);
    mma_gemm_kernel<<<grid, 128, MMA_SMEM>>>(A, lda, aStrE, B0, B1, ldb, bStrE,
                                             C0, C1, ldc, cStrE, M, N, K,
                                             gidx, gstr, cnt, eShift);
}

extern "C" void kernel_launch(void* const* d_in, const int* in_sizes, int n_in,
                              void* d_out, int out_size) {
    (void)in_sizes; (void)n_in; (void)out_size;
    const float* x     = (const float*)d_in[0];
    const float* ln1   = (const float*)d_in[1];
    const float* ln2   = (const float*)d_in[2];
    const float* wq    = (const float*)d_in[3];
    const float* bq    = (const float*)d_in[4];
    const float* wk    = (const float*)d_in[5];
    const float* bk    = (const float*)d_in[6];
    const float* wv    = (const float*)d_in[7];
    const float* bv    = (const float*)d_in[8];
    const float* wo    = (const float*)d_in[9];
    const float* gatew = (const float*)d_in[10];
    const float* eg    = (const float*)d_in[11];
    const float* eu    = (const float*)d_in[12];
    const float* ed    = (const float*)d_in[13];
    const float* sg    = (const float*)d_in[14];
    const float* su    = (const float*)d_in[15];
    const float* sd    = (const float*)d_in[16];
    const float* sgate = (const float*)d_in[17];
    float* out = (float*)d_out;

    cudaFuncSetAttribute(mma_gemm_kernel,
                         cudaFuncAttributeMaxDynamicSharedMemorySize, MMA_SMEM);
    cudaFuncSetAttribute(mma3x_kernel,
                         cudaFuncAttributeMaxDynamicSharedMemorySize, X_SMEM);

    float *hhi, *hlo, *q, *k, *v, *scores, *attn, *ahi, *alo, *x1, *h2, *ch2,
        *gb, *ub, *eo, *sgb, *sub, *sdwn, *gatev, *tokw, *wsp;
    float *ceg, *ceu, *ced, *csg, *csu, *csd;
    int *idx, *cnt, *tokmap;
    cudaGetSymbolAddress((void**)&hhi, g_hhi);
    cudaGetSymbolAddress((void**)&hlo, g_hlo);
    cudaGetSymbolAddress((void**)&q, g_q);
    cudaGetSymbolAddress((void**)&k, g_k);
    cudaGetSymbolAddress((void**)&v, g_v);
    cudaGetSymbolAddress((void**)&scores, g_scores);
    cudaGetSymbolAddress((void**)&attn, g_attn);
    cudaGetSymbolAddress((void**)&ahi, g_ahi);
    cudaGetSymbolAddress((void**)&alo, g_alo);
    cudaGetSymbolAddress((void**)&x1, g_x1);
    cudaGetSymbolAddress((void**)&h2, g_h2);
    cudaGetSymbolAddress((void**)&ch2, g_ch2);
    cudaGetSymbolAddress((void**)&gb, g_gb);
    cudaGetSymbolAddress((void**)&ub, g_ub);
    cudaGetSymbolAddress((void**)&eo, g_eo);
    cudaGetSymbolAddress((void**)&sgb, g_sgb);
    cudaGetSymbolAddress((void**)&sub, g_sub);
    cudaGetSymbolAddress((void**)&sdwn, g_sdwn);
    cudaGetSymbolAddress((void**)&gatev, g_gatev);
    cudaGetSymbolAddress((void**)&idx, g_idx);
    cudaGetSymbolAddress((void**)&cnt, g_cnt);
    cudaGetSymbolAddress((void**)&tokmap, g_tokmap);
    cudaGetSymbolAddress((void**)&tokw, g_tokw);
    cudaGetSymbolAddress((void**)&ceg, g_ceg);
    cudaGetSymbolAddress((void**)&ceu, g_ceu);
    cudaGetSymbolAddress((void**)&ced, g_ced);
    cudaGetSymbolAddress((void**)&csg, g_csg);
    cudaGetSymbolAddress((void**)&csu, g_csu);
    cudaGetSymbolAddress((void**)&csd, g_csd);
    cudaGetSymbolAddress((void**)&wsp, g_wsp);

    const size_t WW = (size_t)H * H;
    const float* wqh = wsp;
    const float* wql = wsp + WW;
    const float* wkh = wsp + 2 * WW;
    const float* wkl = wsp + 3 * WW;
    const float* wvh = wsp + 4 * WW;
    const float* wvl = wsp + 5 * WW;
    const float* woh = wsp + 6 * WW;
    const float* wol = wsp + 7 * WW;

    const float ascale = 0.08838834764831845f;

    // 0a. pre-round MoE/shared weights to tf32 (one launch)
    {
        long long nEG = (long long)E * H * IE / 4;
        long long nED = (long long)E * IE * H / 4;
        long long nSG = (long long)H * IS / 4;
        long long nSD = (long long)IS * H / 4;
        unsigned gx = (unsigned)((nEG + 255) / 256);
        dim3 grid(gx, 6);
        cvt6_kernel<<<grid, 256>>>((const float4*)eg, (float4*)ceg, nEG,
                                   (const float4*)eu, (float4*)ceu, nEG,
                                   (const float4*)ed, (float4*)ced, nED,
                                   (const float4*)sg, (float4*)csg, nSG,
                                   (const float4*)su, (float4*)csu, nSG,
                                   (const float4*)sd, (float4*)csd, nSD);
    }
    // 0b. split attention weights into tf32 hi/lo
    {
        dim3 grid((unsigned)((WW / 4 + 255) / 256), 4);
        split4_kernel<<<grid, 256>>>((const float4*)wq, (const float4*)wk,
                                     (const float4*)wv, (const float4*)wo,
                                     (float4*)wsp);
    }

    // 1. h = rmsnorm(x, ln1), written as hi/lo split
    rmsnorm_kernel<<<S, 256>>>(x, ln1, hhi, nullptr, hlo);

    // 2. q,k,v via 3xTF32 mma (z selects weight/bias/output)
    {
        dim3 grid(16, 16, 3);
        mma3x_kernel<<<grid, 128, X_SMEM>>>(
            hhi, hlo, H, wqh, wql, wkh, wkl, wvh, wvl, NH * D,
            bq, bk, bv, q, k, v, NH * D, nullptr, H);
    }

    // 3. RoPE
    rope_kernel<<<dim3(S, NH), 64>>>(q, k);

    // 4. scores (fp32, lower blocks only)
    {
        dim3 grid(S / 128, S / 128, NH);
        sgemm_kernel<<<grid, 256>>>(q, NH * D, D, k, NH * D, D, scores, S,
                                    (long long)S * S, D, nullptr, nullptr, 0,
                                    1, 1, 0, ascale);
    }

    // 5. softmax
    softmax_kernel<<<dim3(S, NH), 256>>>(scores);

    // 6. attn = probs @ v (fp32)
    {
        dim3 grid(D / 128, S / 128, NH);
        sgemm_kernel<<<grid, 256>>>(scores, S, (long long)S * S, v, NH * D, D,
                                    attn, NH * D, D, S, nullptr, nullptr, 0,
                                    0, 0, 1, 1.0f);
    }

    // 6b. split attn into hi/lo
    {
        long long n4 = (long long)S * H / 4;
        split1_kernel<<<(unsigned)((n4 + 255) / 256), 256>>>(
            (const float4*)attn, (float4*)ahi, (float4*)alo, n4);
    }

    // 7. x1 = x + attn @ wo via 3xTF32 mma
    {
        dim3 grid(16, 16, 1);
        mma3x_kernel<<<grid, 128, X_SMEM>>>(
            ahi, alo, NH * D, woh, wol, nullptr, nullptr, nullptr, nullptr, H,
            nullptr, nullptr, nullptr, x1, nullptr, nullptr, H, x, NH * D);
    }

    // 8. h2 = rmsnorm(x1, ln2) + tf32 copy (fused)
    rmsnorm_kernel<<<S, 256>>>(x1, ln2, h2, ch2, nullptr);

    // 9. router (exact h2)
    cudaMemsetAsync(cnt, 0, E * sizeof(int));
    router_kernel<<<S, 256>>>(h2, gatew, out + (long long)S * H, idx, cnt,
                              tokmap, tokw);

    // 10. MoE gate+up (z = 2E)
    launch_mma(ch2, H, 0, ceg, ceu, IE, (long long)H * IE,
               gb, ub, IE, (long long)S * IE, S, IE, H, idx, S, cnt, 1, 2 * E);

    // 11. silu (+tf32 round)
    {
        dim3 grid((unsigned)(((long long)S * IE + 255) / 256), E);
        silu_mul_expert_kernel<<<grid, 256>>>(gb, ub, cnt);
    }

    // 12. MoE down (z = E)
    launch_mma(gb, IE, (long long)S * IE, ced, nullptr, H, (long long)IE * H,
               eo, nullptr, H, (long long)S * H, S, H, IE, nullptr, 0, cnt, 0, E);

    // 13. shared expert
    launch_mma(ch2, H, 0, csg, csu, IS, 0, sgb, sub, IS, 0, S, IS, H,
               nullptr, 0, nullptr, 1, 2);
    {
        long long n = (long long)S * IS;
        silu_mul_kernel<<<(unsigned)((n + 255) / 256), 256>>>(sgb, sub, n);
    }
    launch_mma(sgb, IS, 0, csd, nullptr, H, 0, sdwn, nullptr, H, 0, S, H, IS,
               nullptr, 0, nullptr, 0, 1);

    // 14. gate scalar
    rowdot_kernel<<<S, 256>>>(h2, sgate, gatev);

    // 15. combine
    final_kernel<<<(S * H) / 256, 256>>>(x1, eo, tokmap, tokw, sdwn, gatev, out);
}

// round 11
// speedup vs baseline: 1.1916x; 1.0343x over previous
#include <cuda_runtime.h>
#include <cuda_bf16.h>
#include <math.h>
#include <float.h>
#include <stdint.h>

#define S 2048
#define H 2048
#define NH 16
#define D 128
#define E 8
#define TOPK 4
#define IE 1408
#define IS 5632

// ---------------- scratch ----------------
__device__ float g_hhi[S * H];
__device__ float g_hlo[S * H];
__device__ float g_q[S * H];
__device__ float g_k[S * H];
__device__ float g_v[S * H];
__device__ float g_qhi[S * H];
__device__ float g_qlo[S * H];
__device__ float g_khi[S * H];
__device__ float g_klo[S * H];
__device__ float g_vhi[S * H];
__device__ float g_vlo[S * H];
__device__ float g_scores[(size_t)NH * S * S];
__device__ float g_slo[(size_t)NH * S * S];
__device__ float g_attn[S * H];
__device__ float g_ahi[S * H];
__device__ float g_alo[S * H];
__device__ float g_x1[S * H];
__device__ float g_h2[S * H];
__device__ float g_ch2[S * H];
__device__ float g_gb[(size_t)E * S * IE];
__device__ float g_ub[(size_t)E * S * IE];
__device__ float g_eo[(size_t)E * S * H];
__device__ float g_sgb[S * IS];
__device__ float g_sub[S * IS];
__device__ float g_sdwn[S * H];
__device__ float g_gatev[S];
__device__ int g_idx[E * S];
__device__ int g_cnt[E];
__device__ int g_tokmap[S * TOPK];
__device__ float g_tokw[S * TOPK];
__device__ float g_ceg[(size_t)E * H * IE];
__device__ float g_ceu[(size_t)E * H * IE];
__device__ float g_ced[(size_t)E * IE * H];
__device__ float g_csg[(size_t)H * IS];
__device__ float g_csu[(size_t)H * IS];
__device__ float g_csd[(size_t)IS * H];
__device__ float g_wsp[(size_t)8 * H * H];

// ================= helpers =================
__device__ __forceinline__ uint32_t smem_to_u32(const void* p) {
    uint32_t a;
    asm("{ .reg .u64 t; cvta.to.shared.u64 t, %1; cvt.u32.u64 %0, t; }"
        : "=r"(a) : "l"(p));
    return a;
}
__device__ __forceinline__ float f2tf32f(float f) {
    uint32_t r;
    asm("cvt.rna.tf32.f32 %0, %1;" : "=r"(r) : "f"(f));
    return __uint_as_float(r);
}
__device__ __forceinline__ void mma_tf32(float* d, const uint32_t* a,
                                         const uint32_t* b) {
    asm volatile(
        "mma.sync.aligned.m16n8k8.row.col.f32.tf32.tf32.f32 "
        "{%0,%1,%2,%3}, {%4,%5,%6,%7}, {%8,%9}, {%0,%1,%2,%3};"
        : "+f"(d[0]), "+f"(d[1]), "+f"(d[2]), "+f"(d[3])
        : "r"(a[0]), "r"(a[1]), "r"(a[2]), "r"(a[3]), "r"(b[0]), "r"(b[1]));
}
__device__ __forceinline__ void cp_async16(uint32_t dst, const void* src) {
    asm volatile("cp.async.ca.shared.global [%0], [%1], 16;"
                 :: "r"(dst), "l"(src));
}

// ================= tf32 mma GEMM v3 (MoE path) ================================
#define APADF 20
#define BPADF 136
#define A_STAGE_B (128 * APADF * 4)
#define B_STAGE_B (16 * BPADF * 4)
#define STAGE_B (A_STAGE_B + B_STAGE_B)
#define MMA_SMEM (STAGE_B * 4)

__global__ __launch_bounds__(128, 2)
void mma_gemm_kernel(const float* __restrict__ A, int lda, long long aStrE,
                     const float* __restrict__ B0, const float* __restrict__ B1,
                     int ldb, long long bStrE,
                     float* __restrict__ C0, float* __restrict__ C1,
                     int ldc, long long cStrE,
                     int M, int N, int K,
                     const int* __restrict__ gidxBase, int gidxStr,
                     const int* __restrict__ cntBase, int eShift) {
    extern __shared__ char smem[];
    const uint32_t sb = smem_to_u32(smem);
    const int z = blockIdx.z;
    const int e = z >> eShift;
    const int which = z & ((1 << eShift) - 1);
    const float* B = (which ? B1 : B0) + (long long)e * bStrE;
    float* C = (which ? C1 : C0) + (long long)e * cStrE;
    A += (long long)e * aStrE;

    const int cnt = cntBase ? cntBase[e] : M;
    const int mEff = min(M, cnt);
    const int row0 = blockIdx.y * 128;
    const int col0 = blockIdx.x * 128;
    if (row0 >= mEff) return;
    const int* gidx = gidxBase ? gidxBase + (long long)e * gidxStr : nullptr;

    const int tid = threadIdx.x;
    const int wid = tid >> 5;
    const int lane = tid & 31;
    const int g = lane >> 2;
    const int t4 = lane & 3;
    const int warpM = wid >> 1;
    const int warpN = wid & 1;

    const float* aG[4];
    uint32_t aS[4];
#pragma unroll
    for (int j = 0; j < 4; j++) {
        int u = tid + 128 * j;
        int m = u >> 2, c4 = u & 3;
        int arow = row0 + m;
        int src;
        if (gidx) src = (arow < cnt) ? gidx[arow] : 0;
        else src = min(arow, M - 1);
        aG[j] = A + (size_t)src * lda + c4 * 4;
        aS[j] = sb + (uint32_t)(m * APADF + c4 * 4) * 4u;
    }
    const float* bG[4];
    uint32_t bS[4];
#pragma unroll
    for (int j = 0; j < 4; j++) {
        int u = tid + 128 * j;
        int n4 = u & 31, kk = u >> 5;
        bG[j] = B + (size_t)kk * ldb + col0 + n4 * 4;
        bS[j] = sb + A_STAGE_B + (uint32_t)(kk * BPADF + n4 * 4) * 4u;
    }

    float acc[4][8][4];
#pragma unroll
    for (int mt = 0; mt < 4; mt++)
#pragma unroll
        for (int nt = 0; nt < 8; nt++)
#pragma unroll
            for (int r = 0; r < 4; r++) acc[mt][nt][r] = 0.f;

    const int nT = K / 16;

#define ISSUE(i)                                                      \
    do {                                                              \
        uint32_t _off = (uint32_t)((i) & 3) * STAGE_B;                \
        int _k0 = (i) * 16;                                           \
        cp_async16(aS[0] + _off, aG[0] + _k0);                        \
        cp_async16(aS[1] + _off, aG[1] + _k0);                        \
        cp_async16(aS[2] + _off, aG[2] + _k0);                        \
        cp_async16(aS[3] + _off, aG[3] + _k0);                        \
        cp_async16(bS[0] + _off, bG[0] + (size_t)_k0 * ldb);          \
        cp_async16(bS[1] + _off, bG[1] + (size_t)_k0 * ldb);          \
        cp_async16(bS[2] + _off, bG[2] + (size_t)_k0 * ldb);          \
        cp_async16(bS[3] + _off, bG[3] + (size_t)_k0 * ldb);          \
        asm volatile("cp.async.commit_group;");                       \
    } while (0)

    ISSUE(0);
    if (nT > 1) ISSUE(1);
    if (nT > 2) ISSUE(2);

    for (int i = 0; i < nT; i++) {
        const int rem = nT - 1 - i;
        if (rem >= 2)
            asm volatile("cp.async.wait_group 2;");
        else if (rem == 1)
            asm volatile("cp.async.wait_group 1;");
        else
            asm volatile("cp.async.wait_group 0;");
        __syncthreads();
        if (i + 3 < nT) ISSUE(i + 3);

        const uint32_t* Asb =
            (const uint32_t*)(smem + (size_t)(i & 3) * STAGE_B);
        const uint32_t* Bsb =
            (const uint32_t*)(smem + (size_t)(i & 3) * STAGE_B + A_STAGE_B);
#pragma unroll
        for (int kk = 0; kk < 16; kk += 8) {
            uint32_t a[4][4], b[8][2];
#pragma unroll
            for (int mt = 0; mt < 4; mt++) {
                int mrow = warpM * 64 + mt * 16;
                a[mt][0] = Asb[(mrow + g) * APADF + kk + t4];
                a[mt][1] = Asb[(mrow + g + 8) * APADF + kk + t4];
                a[mt][2] = Asb[(mrow + g) * APADF + kk + t4 + 4];
                a[mt][3] = Asb[(mrow + g + 8) * APADF + kk + t4 + 4];
            }
#pragma unroll
            for (int nt = 0; nt < 8; nt++) {
                int ncol = warpN * 64 + nt * 8;
                b[nt][0] = Bsb[(kk + t4) * BPADF + ncol + g];
                b[nt][1] = Bsb[(kk + t4 + 4) * BPADF + ncol + g];
            }
#pragma unroll
            for (int mt = 0; mt < 4; mt++)
#pragma unroll
                for (int nt = 0; nt < 8; nt++)
                    mma_tf32(acc[mt][nt], a[mt], b[nt]);
        }
    }
#undef ISSUE

#pragma unroll
    for (int mt = 0; mt < 4; mt++) {
        int rBase = row0 + warpM * 64 + mt * 16 + g;
#pragma unroll
        for (int half = 0; half < 2; half++) {
            int r = rBase + half * 8;
            if (r >= mEff) continue;
            float* cp = C + (size_t)r * ldc;
#pragma unroll
            for (int nt = 0; nt < 8; nt++) {
                int col = col0 + warpN * 64 + nt * 8 + t4 * 2;
                cp[col] = acc[mt][nt][half * 2 + 0];
                cp[col + 1] = acc[mt][nt][half * 2 + 1];
            }
        }
    }
}

// ================= 3xTF32 mma GEMM (QKV / wo) ==========
#define X_APAD 12
#define X_BPAD 136
#define X_A_B (128 * X_APAD * 4)  // 6144
#define X_B_B (8 * X_BPAD * 4)    // 4352
#define X_STAGE (2 * X_A_B + 2 * X_B_B)
#define X_SMEM (X_STAGE * 4)

__global__ __launch_bounds__(128, 2)
void mma3x_kernel(const float* __restrict__ Ahi, const float* __restrict__ Alo,
                  int lda,
                  const float* __restrict__ B0h, const float* __restrict__ B0l,
                  const float* __restrict__ B1h, const float* __restrict__ B1l,
                  const float* __restrict__ B2h, const float* __restrict__ B2l,
                  int ldb,
                  const float* __restrict__ bias0,
                  const float* __restrict__ bias1,
                  const float* __restrict__ bias2,
                  float* __restrict__ C0, float* __restrict__ C1,
                  float* __restrict__ C2, int ldc,
                  const float* __restrict__ residual,
                  int K) {
    extern __shared__ char smem[];
    const uint32_t sb = smem_to_u32(smem);
    const int z = blockIdx.z;
    const float* Bh = (z == 0) ? B0h : (z == 1 ? B1h : B2h);
    const float* Bl = (z == 0) ? B0l : (z == 1 ? B1l : B2l);
    const float* bias = (z == 0) ? bias0 : (z == 1 ? bias1 : bias2);
    float* C = (z == 0) ? C0 : (z == 1 ? C1 : C2);

    const int row0 = blockIdx.y * 128;
    const int col0 = blockIdx.x * 128;

    const int tid = threadIdx.x;
    const int wid = tid >> 5;
    const int lane = tid & 31;
    const int g = lane >> 2;
    const int t4 = lane & 3;
    const int warpM = wid >> 1;
    const int warpN = wid & 1;

    const long long aLoD = Alo - Ahi;
    const long long bLoD = Bl - Bh;

    const float* aGh[2];
    uint32_t aSh[2];
#pragma unroll
    for (int j = 0; j < 2; j++) {
        int u = tid + 128 * j;
        int m = u >> 1, c4 = u & 1;
        aGh[j] = Ahi + (size_t)(row0 + m) * lda + c4 * 4;
        aSh[j] = sb + (uint32_t)(m * X_APAD + c4 * 4) * 4u;
    }
    const float* bGh[2];
    uint32_t bSh[2];
#pragma unroll
    for (int j = 0; j < 2; j++) {
        int u = tid + 128 * j;
        int kk = u >> 5, n4 = u & 31;
        bGh[j] = Bh + (size_t)kk * ldb + col0 + n4 * 4;
        bSh[j] = sb + (uint32_t)(2 * X_A_B) +
                 (uint32_t)(kk * X_BPAD + n4 * 4) * 4u;
    }

    float acc[4][8][4];
#pragma unroll
    for (int mt = 0; mt < 4; mt++)
#pragma unroll
        for (int nt = 0; nt < 8; nt++)
#pragma unroll
            for (int r = 0; r < 4; r++) acc[mt][nt][r] = 0.f;

    const int nT = K / 8;

#define XISSUE(i)                                                       \
    do {                                                                \
        uint32_t _off = (uint32_t)((i) & 3) * X_STAGE;                  \
        int _k0 = (i) * 8;                                              \
        cp_async16(aSh[0] + _off, aGh[0] + _k0);                        \
        cp_async16(aSh[1] + _off, aGh[1] + _k0);                        \
        cp_async16(aSh[0] + X_A_B + _off, aGh[0] + aLoD + _k0);         \
        cp_async16(aSh[1] + X_A_B + _off, aGh[1] + aLoD + _k0);         \
        cp_async16(bSh[0] + _off, bGh[0] + (size_t)_k0 * ldb);          \
        cp_async16(bSh[1] + _off, bGh[1] + (size_t)_k0 * ldb);          \
        cp_async16(bSh[0] + X_B_B + _off, bGh[0] + bLoD + (size_t)_k0 * ldb); \
        cp_async16(bSh[1] + X_B_B + _off, bGh[1] + bLoD + (size_t)_k0 * ldb); \
        asm volatile("cp.async.commit_group;");                         \
    } while (0)

    XISSUE(0);
    XISSUE(1);
    XISSUE(2);

    for (int i = 0; i < nT; i++) {
        const int rem = nT - 1 - i;
        if (rem >= 2)
            asm volatile("cp.async.wait_group 2;");
        else if (rem == 1)
            asm volatile("cp.async.wait_group 1;");
        else
            asm volatile("cp.async.wait_group 0;");
        __syncthreads();
        if (i + 3 < nT) XISSUE(i + 3);

        const uint32_t* Ah = (const uint32_t*)(smem + (size_t)(i & 3) * X_STAGE);
        const uint32_t* Al = Ah + (X_A_B / 4);
        const uint32_t* Bhs =
            (const uint32_t*)(smem + (size_t)(i & 3) * X_STAGE + 2 * X_A_B);
        const uint32_t* Bls = Bhs + (X_B_B / 4);

        uint32_t ah[4][4], al[4][4], bh[8][2], bl[8][2];
#pragma unroll
        for (int mt = 0; mt < 4; mt++) {
            int mrow = warpM * 64 + mt * 16;
            ah[mt][0] = Ah[(mrow + g) * X_APAD + t4];
            ah[mt][1] = Ah[(mrow + g + 8) * X_APAD + t4];
            ah[mt][2] = Ah[(mrow + g) * X_APAD + t4 + 4];
            ah[mt][3] = Ah[(mrow + g + 8) * X_APAD + t4 + 4];
            al[mt][0] = Al[(mrow + g) * X_APAD + t4];
            al[mt][1] = Al[(mrow + g + 8) * X_APAD + t4];
            al[mt][2] = Al[(mrow + g) * X_APAD + t4 + 4];
            al[mt][3] = Al[(mrow + g + 8) * X_APAD + t4 + 4];
        }
#pragma unroll
        for (int nt = 0; nt < 8; nt++) {
            int ncol = warpN * 64 + nt * 8;
            bh[nt][0] = Bhs[t4 * X_BPAD + ncol + g];
            bh[nt][1] = Bhs[(t4 + 4) * X_BPAD + ncol + g];
            bl[nt][0] = Bls[t4 * X_BPAD + ncol + g];
            bl[nt][1] = Bls[(t4 + 4) * X_BPAD + ncol + g];
        }
#pragma unroll
        for (int mt = 0; mt < 4; mt++)
#pragma unroll
            for (int nt = 0; nt < 8; nt++) {
                mma_tf32(acc[mt][nt], ah[mt], bh[nt]);
                mma_tf32(acc[mt][nt], ah[mt], bl[nt]);
                mma_tf32(acc[mt][nt], al[mt], bh[nt]);
            }
    }
#undef XISSUE

#pragma unroll
    for (int mt = 0; mt < 4; mt++) {
        int rBase = row0 + warpM * 64 + mt * 16 + g;
#pragma unroll
        for (int half = 0; half < 2; half++) {
            int r = rBase + half * 8;
            float* cp = C + (size_t)r * ldc;
            const float* rp = residual ? residual + (size_t)r * ldc : nullptr;
#pragma unroll
            for (int nt = 0; nt < 8; nt++) {
                int col = col0 + warpN * 64 + nt * 8 + t4 * 2;
                float v0 = acc[mt][nt][half * 2 + 0];
                float v1 = acc[mt][nt][half * 2 + 1];
                if (bias) {
                    v0 += bias[col];
                    v1 += bias[col + 1];
                }
                if (rp) {
                    v0 += rp[col];
                    v1 += rp[col + 1];
                }
                cp[col] = v0;
                cp[col + 1] = v1;
            }
        }
    }
}

// ================= 3xTF32 scores kernel (Q·K^T, causal) =======================
// Both A (q) and B (k) tiles are 128 rows x 8 dims, hi+lo. 3 stages.
#define SC_HALF (128 * X_APAD * 4)     // 6144
#define SC_STAGE (4 * SC_HALF)         // 24576
#define SC_SMEM (SC_STAGE * 3)         // 73728

__global__ __launch_bounds__(128, 2)
void sc3x_kernel(const float* __restrict__ qhi, const float* __restrict__ qlo,
                 const float* __restrict__ khi, const float* __restrict__ klo,
                 float* __restrict__ scores, float scale) {
    extern __shared__ char smem[];
    const uint32_t sb = smem_to_u32(smem);
    const int h = blockIdx.z;
    const int row0 = blockIdx.y * 128;
    const int col0 = blockIdx.x * 128;
    if (col0 > row0) return;

    const int lda = NH * D;
    const float* Ah = qhi + (size_t)h * D;
    const float* Bh = khi + (size_t)h * D;
    const long long aLoD = qlo - qhi;
    const long long bLoD = klo - khi;

    const int tid = threadIdx.x;
    const int wid = tid >> 5;
    const int lane = tid & 31;
    const int g = lane >> 2;
    const int t4 = lane & 3;
    const int warpM = wid >> 1;
    const int warpN = wid & 1;

    const float* aGh[2];
    uint32_t aSh[2];
    const float* bGh[2];
    uint32_t bSh[2];
#pragma unroll
    for (int j = 0; j < 2; j++) {
        int u = tid + 128 * j;
        int m = u >> 1, c4 = u & 1;
        aGh[j] = Ah + (size_t)(row0 + m) * lda + c4 * 4;
        aSh[j] = sb + (uint32_t)(m * X_APAD + c4 * 4) * 4u;
        bGh[j] = Bh + (size_t)(col0 + m) * lda + c4 * 4;
        bSh[j] = sb + (uint32_t)(2 * SC_HALF) +
                 (uint32_t)(m * X_APAD + c4 * 4) * 4u;
    }

    float acc[4][8][4];
#pragma unroll
    for (int mt = 0; mt < 4; mt++)
#pragma unroll
        for (int nt = 0; nt < 8; nt++)
#pragma unroll
            for (int r = 0; r < 4; r++) acc[mt][nt][r] = 0.f;

    const int nT = D / 8;  // 16
    const uint32_t stOff[3] = {0u, SC_STAGE, 2u * SC_STAGE};

#define SISSUE(i, st)                                                  \
    do {                                                               \
        uint32_t _off = stOff[st];                                     \
        int _k0 = (i) * 8;                                             \
        cp_async16(aSh[0] + _off, aGh[0] + _k0);                       \
        cp_async16(aSh[1] + _off, aGh[1] + _k0);                       \
        cp_async16(aSh[0] + SC_HALF + _off, aGh[0] + aLoD + _k0);      \
        cp_async16(aSh[1] + SC_HALF + _off, aGh[1] + aLoD + _k0);      \
        cp_async16(bSh[0] + _off, bGh[0] + _k0);                       \
        cp_async16(bSh[1] + _off, bGh[1] + _k0);                       \
        cp_async16(bSh[0] + SC_HALF + _off, bGh[0] + bLoD + _k0);      \
        cp_async16(bSh[1] + SC_HALF + _off, bGh[1] + bLoD + _k0);      \
        asm volatile("cp.async.commit_group;");                        \
    } while (0)

    SISSUE(0, 0);
    SISSUE(1, 1);

    int stC = 0, stI = 2;
    for (int i = 0; i < nT; i++) {
        if (i + 1 < nT)
            asm volatile("cp.async.wait_group 1;");
        else
            asm volatile("cp.async.wait_group 0;");
        __syncthreads();
        if (i + 2 < nT) {
            SISSUE(i + 2, stI);
            stI = (stI == 2) ? 0 : stI + 1;
        }
        const uint32_t* Ah2 = (const uint32_t*)(smem + stOff[stC]);
        const uint32_t* Al2 = Ah2 + (SC_HALF / 4);
        const uint32_t* Bh2 = (const uint32_t*)(smem + stOff[stC] + 2 * SC_HALF);
        const uint32_t* Bl2 = Bh2 + (SC_HALF / 4);
        stC = (stC == 2) ? 0 : stC + 1;

        uint32_t ah[4][4], al[4][4], bh[8][2], bl[8][2];
#pragma unroll
        for (int mt = 0; mt < 4; mt++) {
            int mrow = warpM * 64 + mt * 16;
            ah[mt][0] = Ah2[(mrow + g) * X_APAD + t4];
            ah[mt][1] = Ah2[(mrow + g + 8) * X_APAD + t4];
            ah[mt][2] = Ah2[(mrow + g) * X_APAD + t4 + 4];
            ah[mt][3] = Ah2[(mrow + g + 8) * X_APAD + t4 + 4];
            al[mt][0] = Al2[(mrow + g) * X_APAD + t4];
            al[mt][1] = Al2[(mrow + g + 8) * X_APAD + t4];
            al[mt][2] = Al2[(mrow + g) * X_APAD + t4 + 4];
            al[mt][3] = Al2[(mrow + g + 8) * X_APAD + t4 + 4];
        }
#pragma unroll
        for (int nt = 0; nt < 8; nt++) {
            int ncol = warpN * 64 + nt * 8;
            bh[nt][0] = Bh2[(ncol + g) * X_APAD + t4];
            bh[nt][1] = Bh2[(ncol + g) * X_APAD + t4 + 4];
            bl[nt][0] = Bl2[(ncol + g) * X_APAD + t4];
            bl[nt][1] = Bl2[(ncol + g) * X_APAD + t4 + 4];
        }
#pragma unroll
        for (int mt = 0; mt < 4; mt++)
#pragma unroll
            for (int nt = 0; nt < 8; nt++) {
                mma_tf32(acc[mt][nt], ah[mt], bh[nt]);
                mma_tf32(acc[mt][nt], ah[mt], bl[nt]);
                mma_tf32(acc[mt][nt], al[mt], bh[nt]);
            }
    }
#undef SISSUE

    float* Cbase = scores + (size_t)h * S * S;
#pragma unroll
    for (int mt = 0; mt < 4; mt++) {
        int rBase = row0 + warpM * 64 + mt * 16 + g;
#pragma unroll
        for (int half = 0; half < 2; half++) {
            int r = rBase + half * 8;
            float* cp = Cbase + (size_t)r * S;
#pragma unroll
            for (int nt = 0; nt < 8; nt++) {
                int col = col0 + warpN * 64 + nt * 8 + t4 * 2;
                float v0 = acc[mt][nt][half * 2 + 0] * scale;
                float v1 = acc[mt][nt][half * 2 + 1] * scale;
                if (col > r) v0 = -3.4028234663852886e38f;
                if (col + 1 > r) v1 = -3.4028234663852886e38f;
                cp[col] = v0;
                cp[col + 1] = v1;
            }
        }
    }
}

// ================= 3xTF32 PV kernel (probs·V, kLimit) =========================
__global__ __launch_bounds__(128, 2)
void pv3x_kernel(const float* __restrict__ phi, const float* __restrict__ plo,
                 const float* __restrict__ vhi, const float* __restrict__ vlo,
                 float* __restrict__ attn) {
    extern __shared__ char smem[];
    const uint32_t sb = smem_to_u32(smem);
    const int h = blockIdx.z;
    const int row0 = blockIdx.y * 128;

    const int lda = S;
    const int ldb = NH * D;
    const float* Ah = phi + (size_t)h * S * S;
    const float* Bh = vhi + (size_t)h * D;
    const long long aLoD = plo - phi;
    const long long bLoD = vlo - vhi;

    const int tid = threadIdx.x;
    const int wid = tid >> 5;
    const int lane = tid & 31;
    const int g = lane >> 2;
    const int t4 = lane & 3;
    const int warpM = wid >> 1;
    const int warpN = wid & 1;

    const float* aGh[2];
    uint32_t aSh[2];
#pragma unroll
    for (int j = 0; j < 2; j++) {
        int u = tid + 128 * j;
        int m = u >> 1, c4 = u & 1;
        aGh[j] = Ah + (size_t)(row0 + m) * lda + c4 * 4;
        aSh[j] = sb + (uint32_t)(m * X_APAD + c4 * 4) * 4u;
    }
    const float* bGh[2];
    uint32_t bSh[2];
#pragma unroll
    for (int j = 0; j < 2; j++) {
        int u = tid + 128 * j;
        int kk = u >> 5, n4 = u & 31;
        bGh[j] = Bh + (size_t)kk * ldb + n4 * 4;
        bSh[j] = sb + (uint32_t)(2 * X_A_B) +
                 (uint32_t)(kk * X_BPAD + n4 * 4) * 4u;
    }

    float acc[4][8][4];
#pragma unroll
    for (int mt = 0; mt < 4; mt++)
#pragma unroll
        for (int nt = 0; nt < 8; nt++)
#pragma unroll
            for (int r = 0; r < 4; r++) acc[mt][nt][r] = 0.f;

    const int nT = (row0 + 128) / 8;  // >= 16

#define PISSUE(i)                                                       \
    do {                                                                \
        uint32_t _off = (uint32_t)((i) & 3) * X_STAGE;                  \
        int _k0 = (i) * 8;                                              \
        cp_async16(aSh[0] + _off, aGh[0] + _k0);                        \
        cp_async16(aSh[1] + _off, aGh[1] + _k0);                        \
        cp_async16(aSh[0] + X_A_B + _off, aGh[0] + aLoD + _k0);         \
        cp_async16(aSh[1] + X_A_B + _off, aGh[1] + aLoD + _k0);         \
        cp_async16(bSh[0] + _off, bGh[0] + (size_t)_k0 * ldb);          \
        cp_async16(bSh[1] + _off, bGh[1] + (size_t)_k0 * ldb);          \
        cp_async16(bSh[0] + X_B_B + _off, bGh[0] + bLoD + (size_t)_k0 * ldb); \
        cp_async16(bSh[1] + X_B_B + _off, bGh[1] + bLoD + (size_t)_k0 * ldb); \
        asm volatile("cp.async.commit_group;");                         \
    } while (0)

    PISSUE(0);
    PISSUE(1);
    PISSUE(2);

    for (int i = 0; i < nT; i++) {
        const int rem = nT - 1 - i;
        if (rem >= 2)
            asm volatile("cp.async.wait_group 2;");
        else if (rem == 1)
            asm volatile("cp.async.wait_group 1;");
        else
            asm volatile("cp.async.wait_group 0;");
        __syncthreads();
        if (i + 3 < nT) PISSUE(i + 3);

        const uint32_t* Ah2 = (const uint32_t*)(smem + (size_t)(i & 3) * X_STAGE);
        const uint32_t* Al2 = Ah2 + (X_A_B / 4);
        const uint32_t* Bh2 =
            (const uint32_t*)(smem + (size_t)(i & 3) * X_STAGE + 2 * X_A_B);
        const uint32_t* Bl2 = Bh2 + (X_B_B / 4);

        uint32_t ah[4][4], al[4][4], bh[8][2], bl[8][2];
#pragma unroll
        for (int mt = 0; mt < 4; mt++) {
            int mrow = warpM * 64 + mt * 16;
            ah[mt][0] = Ah2[(mrow + g) * X_APAD + t4];
            ah[mt][1] = Ah2[(mrow + g + 8) * X_APAD + t4];
            ah[mt][2] = Ah2[(mrow + g) * X_APAD + t4 + 4];
            ah[mt][3] = Ah2[(mrow + g + 8) * X_APAD + t4 + 4];
            al[mt][0] = Al2[(mrow + g) * X_APAD + t4];
            al[mt][1] = Al2[(mrow + g + 8) * X_APAD + t4];
            al[mt][2] = Al2[(mrow + g) * X_APAD + t4 + 4];
            al[mt][3] = Al2[(mrow + g + 8) * X_APAD + t4 + 4];
        }
#pragma unroll
        for (int nt = 0; nt < 8; nt++) {
            int ncol = warpN * 64 + nt * 8;
            bh[nt][0] = Bh2[t4 * X_BPAD + ncol + g];
            bh[nt][1] = Bh2[(t4 + 4) * X_BPAD + ncol + g];
            bl[nt][0] = Bl2[t4 * X_BPAD + ncol + g];
            bl[nt][1] = Bl2[(t4 + 4) * X_BPAD + ncol + g];
        }
#pragma unroll
        for (int mt = 0; mt < 4; mt++)
#pragma unroll
            for (int nt = 0; nt < 8; nt++) {
                mma_tf32(acc[mt][nt], ah[mt], bh[nt]);
                mma_tf32(acc[mt][nt], ah[mt], bl[nt]);
                mma_tf32(acc[mt][nt], al[mt], bh[nt]);
            }
    }
#undef PISSUE

    float* Cbase = attn + (size_t)h * D;
#pragma unroll
    for (int mt = 0; mt < 4; mt++) {
        int rBase = row0 + warpM * 64 + mt * 16 + g;
#pragma unroll
        for (int half = 0; half < 2; half++) {
            int r = rBase + half * 8;
            float* cp = Cbase + (size_t)r * (NH * D);
#pragma unroll
            for (int nt = 0; nt < 8; nt++) {
                int col = warpN * 64 + nt * 8 + t4 * 2;
                cp[col] = acc[mt][nt][half * 2 + 0];
                cp[col + 1] = acc[mt][nt][half * 2 + 1];
            }
        }
    }
}

// ---------------- weight prep: tf32 cvt (y 0-5) + hi/lo split (y 6-9) --------
__global__ void prep_kernel(const float4* eg, float4* ceg,
                            const float4* eu, float4* ceu,
                            const float4* ed, float4* ced,
                            const float4* sg, float4* csg,
                            const float4* su, float4* csu,
                            const float4* sd, float4* csd,
                            const float4* wq, const float4* wk,
                            const float4* wv, const float4* wo,
                            float4* wsp) {
    const long long nEG = (long long)E * H * IE / 4;
    const long long nED = (long long)E * IE * H / 4;
    const long long nSG = (long long)H * IS / 4;
    const long long nSD = (long long)IS * H / 4;
    const long long nWW = (long long)H * H / 4;
    long long i = (long long)blockIdx.x * 256 + threadIdx.x;
    int y = blockIdx.y;
    if (y < 6) {
        const float4* src;
        float4* dst;
        long long n;
        switch (y) {
            case 0: src = eg; dst = ceg; n = nEG; break;
            case 1: src = eu; dst = ceu; n = nEG; break;
            case 2: src = ed; dst = ced; n = nED; break;
            case 3: src = sg; dst = csg; n = nSG; break;
            case 4: src = su; dst = csu; n = nSG; break;
            default: src = sd; dst = csd; n = nSD; break;
        }
        if (i < n) {
            float4 v = src[i];
            v.x = f2tf32f(v.x);
            v.y = f2tf32f(v.y);
            v.z = f2tf32f(v.z);
            v.w = f2tf32f(v.w);
            dst[i] = v;
        }
    } else {
        const float4* src = (y == 6) ? wq : (y == 7) ? wk : (y == 8) ? wv : wo;
        float4* hi = wsp + (size_t)(2 * (y - 6)) * nWW;
        float4* lo = hi + nWW;
        if (i < nWW) {
            float4 v = src[i];
            float4 hv, lv;
            hv.x = f2tf32f(v.x); lv.x = f2tf32f(v.x - hv.x);
            hv.y = f2tf32f(v.y); lv.y = f2tf32f(v.y - hv.y);
            hv.z = f2tf32f(v.z); lv.z = f2tf32f(v.z - hv.z);
            hv.w = f2tf32f(v.w); lv.w = f2tf32f(v.w - hv.w);
            hi[i] = hv;
            lo[i] = lv;
        }
    }
}

// ---------------- hi/lo split of one tensor ----------------
__global__ void split1_kernel(const float4* __restrict__ src,
                              float4* __restrict__ hi,
                              float4* __restrict__ lo, long long n4) {
    long long i = (long long)blockIdx.x * 256 + threadIdx.x;
    if (i < n4) {
        float4 v = src[i];
        float4 hv, lv;
        hv.x = f2tf32f(v.x); lv.x = f2tf32f(v.x - hv.x);
        hv.y = f2tf32f(v.y); lv.y = f2tf32f(v.y - hv.y);
        hv.z = f2tf32f(v.z); lv.z = f2tf32f(v.z - hv.z);
        hv.w = f2tf32f(v.w); lv.w = f2tf32f(v.w - hv.w);
        hi[i] = hv;
        lo[i] = lv;
    }
}

// ---------------- RMSNorm: plain / +tf32 copy / hi+lo split ----------------
__global__ void rmsnorm_kernel(const float* __restrict__ x,
                               const float* __restrict__ w,
                               float* __restrict__ out,
                               float* __restrict__ outTf,
                               float* __restrict__ outLo) {
    const float* xr = x + (long long)blockIdx.x * H;
    float* orow = out + (long long)blockIdx.x * H;
    __shared__ float red[256];
    float s = 0.f;
    for (int j = threadIdx.x; j < H; j += 256) {
        float v = xr[j];
        s += v * v;
    }
    red[threadIdx.x] = s;
    __syncthreads();
    for (int st = 128; st > 0; st >>= 1) {
        if (threadIdx.x < st) red[threadIdx.x] += red[threadIdx.x + st];
        __syncthreads();
    }
    float inv = 1.0f / sqrtf(red[0] / (float)H + 1e-6f);
    if (outLo) {
        float* lrow = outLo + (long long)blockIdx.x * H;
        for (int j = threadIdx.x; j < H; j += 256) {
            float v = w[j] * xr[j] * inv;
            float hi = f2tf32f(v);
            orow[j] = hi;
            lrow[j] = f2tf32f(v - hi);
        }
    } else if (outTf) {
        float* trow = outTf + (long long)blockIdx.x * H;
        for (int j = threadIdx.x; j < H; j += 256) {
            float v = w[j] * xr[j] * inv;
            orow[j] = v;
            trow[j] = f2tf32f(v);
        }
    } else {
        for (int j = threadIdx.x; j < H; j += 256) orow[j] = w[j] * xr[j] * inv;
    }
}

// ---------------- RoPE: rotate + hi/lo split ----------------
__global__ void rope_kernel(const float* __restrict__ q,
                            const float* __restrict__ k,
                            float* __restrict__ qhi, float* __restrict__ qlo,
                            float* __restrict__ khi, float* __restrict__ klo) {
    int s = blockIdx.x;
    int h = blockIdx.y;
    int j = threadIdx.x;
    float inv = exp2f(-(float)j * 0.31143075889569023f);
    float ang = (float)s * inv;
    float c, sn;
    sincosf(ang, &sn, &c);
    long long base = ((long long)s * NH + h) * D;
    float q1 = q[base + j], q2 = q[base + j + 64];
    float k1 = k[base + j], k2 = k[base + j + 64];
    float qa = q1 * c - q2 * sn;
    float qb = q2 * c + q1 * sn;
    float ka = k1 * c - k2 * sn;
    float kb = k2 * c + k1 * sn;
    float t;
    t = f2tf32f(qa); qhi[base + j] = t; qlo[base + j] = f2tf32f(qa - t);
    t = f2tf32f(qb); qhi[base + j + 64] = t; qlo[base + j + 64] = f2tf32f(qb - t);
    t = f2tf32f(ka); khi[base + j] = t; klo[base + j] = f2tf32f(ka - t);
    t = f2tf32f(kb); khi[base + j + 64] = t; klo[base + j + 64] = f2tf32f(kb - t);
}

// ---------------- causal row softmax, hi/lo output ----------------
__global__ void softmax_kernel(float* __restrict__ scores,
                               float* __restrict__ slo) {
    int r = blockIdx.x;
    float* row = scores + ((size_t)blockIdx.y * S + r) * S;
    float* lrow = slo + ((size_t)blockIdx.y * S + r) * S;
    const int limit = r + 1;
    const int rBlk = ((r >> 7) + 1) << 7;
    __shared__ float red[256];
    int tid = threadIdx.x;
    float m = -FLT_MAX;
    for (int j = tid; j < limit; j += 256) m = fmaxf(m, row[j]);
    red[tid] = m;
    __syncthreads();
    for (int st = 128; st > 0; st >>= 1) {
        if (tid < st) red[tid] = fmaxf(red[tid], red[tid + st]);
        __syncthreads();
    }
    m = red[0];
    __syncthreads();
    float sum = 0.f;
    for (int j = tid; j < limit; j += 256) {
        float e = expf(row[j] - m);
        row[j] = e;
        sum += e;
    }
    red[tid] = sum;
    __syncthreads();
    for (int st = 128; st > 0; st >>= 1) {
        if (tid < st) red[tid] += red[tid + st];
        __syncthreads();
    }
    float inv = 1.0f / red[0];
    for (int j = tid; j < limit; j += 256) {
        float p = row[j] * inv;
        float hi = f2tf32f(p);
        row[j] = hi;
        lrow[j] = f2tf32f(p - hi);
    }
    for (int j = limit + tid; j < rBlk; j += 256) {
        row[j] = 0.f;
        lrow[j] = 0.f;
    }
}

// ---------------- router ----------------
__global__ void router_kernel(const float* __restrict__ h2,
                              const float* __restrict__ gate_w,
                              float* __restrict__ logits_out,
                              int* __restrict__ idxbuf,
                              int* __restrict__ cnt,
                              int* __restrict__ tokmap,
                              float* __restrict__ tokw) {
    int s = blockIdx.x;
    const float* hr = h2 + (long long)s * H;
    __shared__ float red[256][E];
    float p[E];
#pragma unroll
    for (int e = 0; e < E; e++) p[e] = 0.f;
    for (int j = threadIdx.x; j < H; j += 256) {
        float hv = hr[j];
#pragma unroll
        for (int e = 0; e < E; e++) p[e] += hv * gate_w[j * E + e];
    }
#pragma unroll
    for (int e = 0; e < E; e++) red[threadIdx.x][e] = p[e];
    __syncthreads();
    for (int st = 128; st > 0; st >>= 1) {
        if (threadIdx.x < st)
#pragma unroll
            for (int e = 0; e < E; e++) red[threadIdx.x][e] += red[threadIdx.x + st][e];
        __syncthreads();
    }
    if (threadIdx.x == 0) {
        float logit[E];
        float m = -FLT_MAX;
#pragma unroll
        for (int e = 0; e < E; e++) {
            logit[e] = red[0][e];
            logits_out[(long long)s * E + e] = logit[e];
            m = fmaxf(m, logit[e]);
        }
        float sum = 0.f, rw[E];
#pragma unroll
        for (int e = 0; e < E; e++) {
            rw[e] = expf(logit[e] - m);
            sum += rw[e];
        }
        float inv = 1.0f / sum;
#pragma unroll
        for (int e = 0; e < E; e++) rw[e] *= inv;
        bool used[E];
#pragma unroll
        for (int e = 0; e < E; e++) used[e] = false;
        for (int k = 0; k < TOPK; k++) {
            int best = -1;
            float bvv = -FLT_MAX;
            for (int e = 0; e < E; e++)
                if (!used[e] && rw[e] > bvv) { bvv = rw[e]; best = e; }
            used[best] = true;
            int pos = atomicAdd(&cnt[best], 1);
            idxbuf[best * S + pos] = s;
            tokmap[s * TOPK + k] = best * S + pos;
            tokw[s * TOPK + k] = bvv;
        }
    }
}

// ---------------- h2 . sgate ----------------
__global__ void rowdot_kernel(const float* __restrict__ h2,
                              const float* __restrict__ sgate,
                              float* __restrict__ gatev) {
    int s = blockIdx.x;
    const float* hr = h2 + (long long)s * H;
    __shared__ float red[256];
    float acc = 0.f;
    for (int j = threadIdx.x; j < H; j += 256) acc += hr[j] * sgate[j];
    red[threadIdx.x] = acc;
    __syncthreads();
    for (int st = 128; st > 0; st >>= 1) {
        if (threadIdx.x < st) red[threadIdx.x] += red[threadIdx.x + st];
        __syncthreads();
    }
    if (threadIdx.x == 0) gatev[s] = red[0];
}

// ---------------- silu kernels ----------------
__global__ void silu_mul_expert_kernel(float* __restrict__ gb,
                                       const float* __restrict__ ub,
                                       const int* __restrict__ cnt) {
    int e = blockIdx.y;
    long long i = (long long)blockIdx.x * 256 + threadIdx.x;
    long long lim = (long long)cnt[e] * IE;
    if (i >= lim) return;
    size_t o = (size_t)e * S * IE + i;
    float x = gb[o];
    float sg = 1.0f / (1.0f + expf(-x));
    gb[o] = f2tf32f(x * sg * ub[o]);
}
__global__ void silu_mul_kernel(float* __restrict__ g, const float* __restrict__ u,
                                long long n) {
    long long i = (long long)blockIdx.x * 256 + threadIdx.x;
    if (i < n) {
        float x = g[i];
        float sg = 1.0f / (1.0f + expf(-x));
        g[i] = f2tf32f(x * sg * u[i]);
    }
}

// ---------------- final combine ----------------
__global__ void final_kernel(const float* __restrict__ x1,
                             const float* __restrict__ eo,
                             const int* __restrict__ tokmap,
                             const float* __restrict__ tokw,
                             const float* __restrict__ sdwn,
                             const float* __restrict__ gatev,
                             float* __restrict__ out) {
    long long i = (long long)blockIdx.x * 256 + threadIdx.x;
    int s = (int)(i / H);
    int c = (int)(i % H);
    float gv = 1.0f / (1.0f + expf(-gatev[s]));
    float acc = x1[i] + gv * sdwn[i];
#pragma unroll
    for (int j = 0; j < TOPK; j++) {
        int row = tokmap[s * TOPK + j];
        acc += tokw[s * TOPK + j] * eo[(size_t)row * H + c];
    }
    out[i] = acc;
}

// ---------------- host ----------------
static void launch_mma(const float* A, int lda, long long aStrE,
                       const float* B0, const float* B1, int ldb, long long bStrE,
                       float* C0, float* C1, int ldc, long long cStrE,
                       int M, int N, int K,
                       const int* gidx, int gstr, const int* cnt, int eShift,
                       int nz) {
    dim3 grid(N / 128, (M + 127) / 128, nz);
    mma_gemm_kernel<<<grid, 128, MMA_SMEM>>>(A, lda, aStrE, B0, B1, ldb, bStrE,
                                             C0, C1, ldc, cStrE, M, N, K,
                                             gidx, gstr, cnt, eShift);
}

extern "C" void kernel_launch(void* const* d_in, const int* in_sizes, int n_in,
                              void* d_out, int out_size) {
    (void)in_sizes; (void)n_in; (void)out_size;
    const float* x     = (const float*)d_in[0];
    const float* ln1   = (const float*)d_in[1];
    const float* ln2   = (const float*)d_in[2];
    const float* wq    = (const float*)d_in[3];
    const float* bq    = (const float*)d_in[4];
    const float* wk    = (const float*)d_in[5];
    const float* bk    = (const float*)d_in[6];
    const float* wv    = (const float*)d_in[7];
    const float* bv    = (const float*)d_in[8];
    const float* wo    = (const float*)d_in[9];
    const float* gatew = (const float*)d_in[10];
    const float* eg    = (const float*)d_in[11];
    const float* eu    = (const float*)d_in[12];
    const float* ed    = (const float*)d_in[13];
    const float* sg    = (const float*)d_in[14];
    const float* su    = (const float*)d_in[15];
    const float* sd    = (const float*)d_in[16];
    const float* sgate = (const float*)d_in[17];
    float* out = (float*)d_out;

    cudaFuncSetAttribute(mma_gemm_kernel,
                         cudaFuncAttributeMaxDynamicSharedMemorySize, MMA_SMEM);
    cudaFuncSetAttribute(mma3x_kernel,
                         cudaFuncAttributeMaxDynamicSharedMemorySize, X_SMEM);
    cudaFuncSetAttribute(sc3x_kernel,
                         cudaFuncAttributeMaxDynamicSharedMemorySize, SC_SMEM);
    cudaFuncSetAttribute(pv3x_kernel,
                         cudaFuncAttributeMaxDynamicSharedMemorySize, X_SMEM);

    float *hhi, *hlo, *q, *k, *v, *qhi, *qlo, *khi, *klo, *vhi, *vlo, *scores,
        *slo, *attn, *ahi, *alo, *x1, *h2, *ch2, *gb, *ub, *eo, *sgb, *sub,
        *sdwn, *gatev, *tokw, *wsp;
    float *ceg, *ceu, *ced, *csg, *csu, *csd;
    int *idx, *cnt, *tokmap;
    cudaGetSymbolAddress((void**)&hhi, g_hhi);
    cudaGetSymbolAddress((void**)&hlo, g_hlo);
    cudaGetSymbolAddress((void**)&q, g_q);
    cudaGetSymbolAddress((void**)&k, g_k);
    cudaGetSymbolAddress((void**)&v, g_v);
    cudaGetSymbolAddress((void**)&qhi, g_qhi);
    cudaGetSymbolAddress((void**)&qlo, g_qlo);
    cudaGetSymbolAddress((void**)&khi, g_khi);
    cudaGetSymbolAddress((void**)&klo, g_klo);
    cudaGetSymbolAddress((void**)&vhi, g_vhi);
    cudaGetSymbolAddress((void**)&vlo, g_vlo);
    cudaGetSymbolAddress((void**)&scores, g_scores);
    cudaGetSymbolAddress((void**)&slo, g_slo);
    cudaGetSymbolAddress((void**)&attn, g_attn);
    cudaGetSymbolAddress((void**)&ahi, g_ahi);
    cudaGetSymbolAddress((void**)&alo, g_alo);
    cudaGetSymbolAddress((void**)&x1, g_x1);
    cudaGetSymbolAddress((void**)&h2, g_h2);
    cudaGetSymbolAddress((void**)&ch2, g_ch2);
    cudaGetSymbolAddress((void**)&gb, g_gb);
    cudaGetSymbolAddress((void**)&ub, g_ub);
    cudaGetSymbolAddress((void**)&eo, g_eo);
    cudaGetSymbolAddress((void**)&sgb, g_sgb);
    cudaGetSymbolAddress((void**)&sub, g_sub);
    cudaGetSymbolAddress((void**)&sdwn, g_sdwn);
    cudaGetSymbolAddress((void**)&gatev, g_gatev);
    cudaGetSymbolAddress((void**)&idx, g_idx);
    cudaGetSymbolAddress((void**)&cnt, g_cnt);
    cudaGetSymbolAddress((void**)&tokmap, g_tokmap);
    cudaGetSymbolAddress((void**)&tokw, g_tokw);
    cudaGetSymbolAddress((void**)&ceg, g_ceg);
    cudaGetSymbolAddress((void**)&ceu, g_ceu);
    cudaGetSymbolAddress((void**)&ced, g_ced);
    cudaGetSymbolAddress((void**)&csg, g_csg);
    cudaGetSymbolAddress((void**)&csu, g_csu);
    cudaGetSymbolAddress((void**)&csd, g_csd);
    cudaGetSymbolAddress((void**)&wsp, g_wsp);

    const size_t WW = (size_t)H * H;
    const float* wqh = wsp;
    const float* wql = wsp + WW;
    const float* wkh = wsp + 2 * WW;
    const float* wkl = wsp + 3 * WW;
    const float* wvh = wsp + 4 * WW;
    const float* wvl = wsp + 5 * WW;
    const float* woh = wsp + 6 * WW;
    const float* wol = wsp + 7 * WW;

    const float ascale = 0.08838834764831845f;

    // 0. weight prep: tf32 round (MoE) + hi/lo split (attention) in one launch
    {
        long long nEG = (long long)E * H * IE / 4;
        unsigned gx = (unsigned)((nEG + 255) / 256);
        dim3 grid(gx, 10);
        prep_kernel<<<grid, 256>>>(
            (const float4*)eg, (float4*)ceg, (const float4*)eu, (float4*)ceu,
            (const float4*)ed, (float4*)ced, (const float4*)sg, (float4*)csg,
            (const float4*)su, (float4*)csu, (const float4*)sd, (float4*)csd,
            (const float4*)wq, (const float4*)wk, (const float4*)wv,
            (const float4*)wo, (float4*)wsp);
    }

    // 1. h = rmsnorm(x, ln1), hi/lo split
    rmsnorm_kernel<<<S, 256>>>(x, ln1, hhi, nullptr, hlo);

    // 2. q,k,v via 3xTF32
    {
        dim3 grid(16, 16, 3);
        mma3x_kernel<<<grid, 128, X_SMEM>>>(
            hhi, hlo, H, wqh, wql, wkh, wkl, wvh, wvl, NH * D,
            bq, bk, bv, q, k, v, NH * D, nullptr, H);
    }

    // 3. RoPE + q/k hi-lo split; v hi/lo split
    rope_kernel<<<dim3(S, NH), 64>>>(q, k, qhi, qlo, khi, klo);
    {
        long long n4 = (long long)S * H / 4;
        split1_kernel<<<(unsigned)((n4 + 255) / 256), 256>>>(
            (const float4*)v, (float4*)vhi, (float4*)vlo, n4);
    }

    // 4. scores via 3xTF32 (causal blocks only)
    {
        dim3 grid(S / 128, S / 128, NH);
        sc3x_kernel<<<grid, 128, SC_SMEM>>>(qhi, qlo, khi, klo, scores, ascale);
    }

    // 5. softmax -> probs hi (in place) + lo
    softmax_kernel<<<dim3(S, NH), 256>>>(scores, slo);

    // 6. attn = probs @ v via 3xTF32 (K bounded at diagonal)
    {
        dim3 grid(1, S / 128, NH);
        pv3x_kernel<<<grid, 128, X_SMEM>>>(scores, slo, vhi, vlo, attn);
    }

    // 6b. split attn
    {
        long long n4 = (long long)S * H / 4;
        split1_kernel<<<(unsigned)((n4 + 255) / 256), 256>>>(
            (const float4*)attn, (float4*)ahi, (float4*)alo, n4);
    }

    // 7. x1 = x + attn @ wo via 3xTF32
    {
        dim3 grid(16, 16, 1);
        mma3x_kernel<<<grid, 128, X_SMEM>>>(
            ahi, alo, NH * D, woh, wol, nullptr, nullptr, nullptr, nullptr, H,
            nullptr, nullptr, nullptr, x1, nullptr, nullptr, H, x, NH * D);
    }

    // 8. h2 = rmsnorm(x1, ln2) + tf32 copy
    rmsnorm_kernel<<<S, 256>>>(x1, ln2, h2, ch2, nullptr);

    // 9. router
    cudaMemsetAsync(cnt, 0, E * sizeof(int));
    router_kernel<<<S, 256>>>(h2, gatew, out + (long long)S * H, idx, cnt,
                              tokmap, tokw);

    // 10. MoE gate+up
    launch_mma(ch2, H, 0, ceg, ceu, IE, (long long)H * IE,
               gb, ub, IE, (long long)S * IE, S, IE, H, idx, S, cnt, 1, 2 * E);

    // 11. silu
    {
        dim3 grid((unsigned)(((long long)S * IE + 255) / 256), E);
        silu_mul_expert_kernel<<<grid, 256>>>(gb, ub, cnt);
    }

    // 12. MoE down
    launch_mma(gb, IE, (long long)S * IE, ced, nullptr, H, (long long)IE * H,
               eo, nullptr, H, (long long)S * H, S, H, IE, nullptr, 0, cnt, 0, E);

    // 13. shared expert
    launch_mma(ch2, H, 0, csg, csu, IS, 0, sgb, sub, IS, 0, S, IS, H,
               nullptr, 0, nullptr, 1, 2);
    {
        long long n = (long long)S * IS;
        silu_mul_kernel<<<(unsigned)((n + 255) / 256), 256>>>(sgb, sub, n);
    }
    launch_mma(sgb, IS, 0, csd, nullptr, H, 0, sdwn, nullptr, H, 0, S, H, IS,
               nullptr, 0, nullptr, 0, 1);

    // 14. gate scalar
    rowdot_kernel<<<S, 256>>>(h2, sgate, gatev);

    // 15. combine
    final_kernel<<<(S * H) / 256, 256>>>(x1, eo, tokmap, tokw, sdwn, gatev, out);
}